// round 2
// baseline (speedup 1.0000x reference)
#include <cuda_runtime.h>
#include <math.h>

// ---- problem constants ----
#define BATCH   8
#define TT      256
#define BT      2048          // BATCH*TT
#define DM      256           // d_model
#define DI      512           // d_inner
#define DS      16            // d_state
#define DTR     16            // dt_rank

// ---- scratch (device globals; no allocation allowed) ----
__device__ float  g_f1[2048*16*32*32];   // conv1 out
__device__ float  g_f2[2048*32*16*16];   // conv2 out
__device__ float  g_z1[2048*32];         // pooled CNN features
__device__ float  g_h [BT*DM];           // residual stream
__device__ float  g_xn[BT*DM];           // rmsnorm output
__device__ float  g_xz[BT*2*DI];         // in_proj output (xin | z)
__device__ float  g_xin[BT*DI];          // conv1d+silu output
__device__ float  g_dt[BT*DTR];          // dt part of x_proj
__device__ float2 g_bc[BT*DS];           // (B,C) interleaved
__device__ float2 g_du[BT*DI];           // (delta, u) interleaved
__device__ float  g_y [BT*DI];           // scan output gated
__device__ float  g_hh[BT*64];           // head hidden
__device__ float  g_logits[BT];

// =====================================================================
// CNN
// =====================================================================
__global__ __launch_bounds__(512) void conv1_kernel(const float* __restrict__ x,
                             const float* __restrict__ w,
                             const float* __restrict__ b,
                             float* __restrict__ out)
{
    // x: (2048,1,64,64) -> out: (2048,16,32,32), stride2 SAME (pad hi=1), relu
    __shared__ float sin[65*65];
    __shared__ float sw[144];
    __shared__ float sb[16];
    int f = blockIdx.x;
    const float* xf = x + (size_t)f*4096;
    for (int i = threadIdx.x; i < 65*65; i += 512) {
        int r = i / 65, c = i - r*65;
        sin[i] = (r < 64 && c < 64) ? xf[r*64+c] : 0.f;
    }
    if (threadIdx.x < 144) sw[threadIdx.x] = w[threadIdx.x];
    if (threadIdx.x < 16)  sb[threadIdx.x] = b[threadIdx.x];
    __syncthreads();
    int xg = threadIdx.x & 3;            // ox group (8 outputs)
    int oy = (threadIdx.x >> 2) & 31;    // output row
    int cq = threadIdx.x >> 7;           // co quad (4 channels)
    float acc[4][8];
    #pragma unroll
    for (int c = 0; c < 4; c++) {
        float bb = sb[cq*4+c];
        #pragma unroll
        for (int q = 0; q < 8; q++) acc[c][q] = bb;
    }
    int i0 = oy*2, j0 = xg*16;
    #pragma unroll
    for (int ky = 0; ky < 3; ky++) {
        const float* rp = sin + (i0+ky)*65 + j0;
        float r[17];
        #pragma unroll
        for (int t = 0; t < 17; t++) r[t] = rp[t];
        #pragma unroll
        for (int c = 0; c < 4; c++) {
            const float* wp = sw + (cq*4+c)*9 + ky*3;
            float w0 = wp[0], w1 = wp[1], w2 = wp[2];
            #pragma unroll
            for (int q = 0; q < 8; q++)
                acc[c][q] = fmaf(r[2*q],w0, fmaf(r[2*q+1],w1, fmaf(r[2*q+2],w2, acc[c][q])));
        }
    }
    #pragma unroll
    for (int c = 0; c < 4; c++)
        #pragma unroll
        for (int q = 0; q < 8; q++)
            out[((size_t)f*16 + cq*4+c)*1024 + oy*32 + xg*8 + q] = fmaxf(acc[c][q], 0.f);
}

__global__ __launch_bounds__(64) void conv2_kernel(const float* __restrict__ in,
                             const float* __restrict__ w,
                             const float* __restrict__ b,
                             float* __restrict__ out)
{
    // in (2048,16,32,32) -> out (2048,32,16,16), grid (2048,4 quadrants), 64 thr
    __shared__ float sin[16*17*17];   // 18.5KB
    __shared__ float sw[32*16*9];     // 18.4KB
    int f  = blockIdx.x;
    int qy = blockIdx.y >> 1, qx = blockIdx.y & 1;
    for (int idx = threadIdx.x; idx < 16*17*17; idx += 64) {
        int ci = idx / 289;
        int rem = idx - ci*289;
        int i = rem / 17, j = rem - i*17;
        int gi = qy*16 + i, gj = qx*16 + j;
        sin[idx] = (gi < 32 && gj < 32) ? in[(size_t)f*16384 + ci*1024 + gi*32 + gj] : 0.f;
    }
    for (int idx = threadIdx.x; idx < 32*16*9; idx += 64) sw[idx] = w[idx];
    __syncthreads();
    int cg = threadIdx.x >> 3;     // 0..7 (4 co each)
    int oy = threadIdx.x & 7;      // 0..7 local
    float acc[4][8];
    #pragma unroll
    for (int c = 0; c < 4; c++) {
        float bb = __ldg(&b[cg*4+c]);
        #pragma unroll
        for (int q = 0; q < 8; q++) acc[c][q] = bb;
    }
    #pragma unroll 1
    for (int ci = 0; ci < 16; ci++) {
        const float* base = sin + ci*289;
        const float* rp0 = base + (2*oy+0)*17;
        const float* rp1 = base + (2*oy+1)*17;
        const float* rp2 = base + (2*oy+2)*17;
        float r0[17], r1[17], r2[17];
        #pragma unroll
        for (int t = 0; t < 17; t++) { r0[t]=rp0[t]; r1[t]=rp1[t]; r2[t]=rp2[t]; }
        #pragma unroll
        for (int c = 0; c < 4; c++) {
            const float* wp = sw + ((cg*4+c)*16 + ci)*9;
            float w0=wp[0],w1=wp[1],w2=wp[2],w3=wp[3],w4=wp[4],w5=wp[5],w6=wp[6],w7=wp[7],w8=wp[8];
            #pragma unroll
            for (int q = 0; q < 8; q++) {
                float a = acc[c][q];
                int j0 = 2*q;
                a = fmaf(r0[j0],w0,a); a = fmaf(r0[j0+1],w1,a); a = fmaf(r0[j0+2],w2,a);
                a = fmaf(r1[j0],w3,a); a = fmaf(r1[j0+1],w4,a); a = fmaf(r1[j0+2],w5,a);
                a = fmaf(r2[j0],w6,a); a = fmaf(r2[j0+1],w7,a); a = fmaf(r2[j0+2],w8,a);
                acc[c][q] = a;
            }
        }
    }
    #pragma unroll
    for (int c = 0; c < 4; c++)
        #pragma unroll
        for (int q = 0; q < 8; q++)
            out[((size_t)f*32 + cg*4+c)*256 + (qy*8+oy)*16 + qx*8 + q] = fmaxf(acc[c][q], 0.f);
}

__global__ __launch_bounds__(64) void conv3pool_kernel(const float* __restrict__ in,
                                 const float* __restrict__ w,
                                 const float* __restrict__ b,
                                 float* __restrict__ z1)
{
    // in (2048,32,16,16) -> conv (32,8,8) relu -> mean -> z1 (2048,32)
    __shared__ float sin[32*17*17]; // 37KB
    int f = blockIdx.x;
    for (int idx = threadIdx.x; idx < 32*17*17; idx += 64) {
        int ci = idx / 289;
        int rem = idx - ci*289;
        int i = rem / 17, j = rem - i*17;
        sin[idx] = (i < 16 && j < 16) ? in[(size_t)f*8192 + ci*256 + i*16 + j] : 0.f;
    }
    __syncthreads();
    int cg = threadIdx.x >> 3;   // 0..7 (4 co each)
    int oy = threadIdx.x & 7;
    float acc[4][8];
    #pragma unroll
    for (int c = 0; c < 4; c++) {
        float bb = __ldg(&b[cg*4+c]);
        #pragma unroll
        for (int q = 0; q < 8; q++) acc[c][q] = bb;
    }
    #pragma unroll 1
    for (int ci = 0; ci < 32; ci++) {
        const float* base = sin + ci*289;
        const float* rp0 = base + (2*oy+0)*17;
        const float* rp1 = base + (2*oy+1)*17;
        const float* rp2 = base + (2*oy+2)*17;
        float r0[17], r1[17], r2[17];
        #pragma unroll
        for (int t = 0; t < 17; t++) { r0[t]=rp0[t]; r1[t]=rp1[t]; r2[t]=rp2[t]; }
        #pragma unroll
        for (int c = 0; c < 4; c++) {
            const float* wp = w + ((cg*4+c)*32 + ci)*9;
            float w0=__ldg(wp+0),w1=__ldg(wp+1),w2=__ldg(wp+2),w3=__ldg(wp+3),w4=__ldg(wp+4),
                  w5=__ldg(wp+5),w6=__ldg(wp+6),w7=__ldg(wp+7),w8=__ldg(wp+8);
            #pragma unroll
            for (int q = 0; q < 8; q++) {
                float a = acc[c][q];
                int j0 = 2*q;
                a = fmaf(r0[j0],w0,a); a = fmaf(r0[j0+1],w1,a); a = fmaf(r0[j0+2],w2,a);
                a = fmaf(r1[j0],w3,a); a = fmaf(r1[j0+1],w4,a); a = fmaf(r1[j0+2],w5,a);
                a = fmaf(r2[j0],w6,a); a = fmaf(r2[j0+1],w7,a); a = fmaf(r2[j0+2],w8,a);
                acc[c][q] = a;
            }
        }
    }
    #pragma unroll
    for (int c = 0; c < 4; c++) {
        float s = 0.f;
        #pragma unroll
        for (int q = 0; q < 8; q++) s += fmaxf(acc[c][q], 0.f);
        // reduce over 8 oy threads (consecutive lanes)
        #pragma unroll
        for (int o = 4; o > 0; o >>= 1) s += __shfl_down_sync(0xffffffffu, s, o, 8);
        if (oy == 0) z1[f*32 + cg*4 + c] = s * (1.f/64.f);
    }
}

__global__ __launch_bounds__(256) void fc_kernel(const float* __restrict__ z1,
                          const float* __restrict__ w,
                          const float* __restrict__ b,
                          float* __restrict__ h)
{
    // block = 32 tokens, thread = one output j; w row in regs
    __shared__ float sz[32*33];
    int tok0 = blockIdx.x * 32;
    int j = threadIdx.x;
    for (int idx = threadIdx.x; idx < 1024; idx += 256) {
        int t = idx >> 5, k = idx & 31;
        sz[t*33 + k] = z1[(tok0+t)*32 + k];
    }
    __syncthreads();
    float wr[32];
    #pragma unroll
    for (int k = 0; k < 32; k++) wr[k] = w[j*32 + k];
    float bb = b[j];
    for (int t = 0; t < 32; t++) {
        float acc = bb;
        const float* zr = sz + t*33;
        #pragma unroll
        for (int k = 0; k < 32; k++) acc = fmaf(zr[k], wr[k], acc);
        h[(size_t)(tok0+t)*256 + j] = acc;
    }
}

// =====================================================================
// Mamba pieces
// =====================================================================
__global__ __launch_bounds__(256) void rmsnorm_kernel(const float* __restrict__ x,
                               const float* __restrict__ w,
                               float* __restrict__ out)
{
    // warp per token
    int tok = blockIdx.x*8 + (threadIdx.x >> 5);
    int lane = threadIdx.x & 31;
    const float4* xr = (const float4*)(x + (size_t)tok*256);
    float4 v0 = xr[lane*2], v1 = xr[lane*2+1];
    float ss = v0.x*v0.x + v0.y*v0.y + v0.z*v0.z + v0.w*v0.w
             + v1.x*v1.x + v1.y*v1.y + v1.z*v1.z + v1.w*v1.w;
    #pragma unroll
    for (int o = 16; o > 0; o >>= 1) ss += __shfl_xor_sync(0xffffffffu, ss, o);
    float scale = rsqrtf(ss * (1.f/256.f) + 1e-5f);
    const float4* wr = (const float4*)w;
    float4 w0 = wr[lane*2], w1 = wr[lane*2+1];
    float4 o0, o1;
    o0.x = v0.x*scale*w0.x; o0.y = v0.y*scale*w0.y; o0.z = v0.z*scale*w0.z; o0.w = v0.w*scale*w0.w;
    o1.x = v1.x*scale*w1.x; o1.y = v1.y*scale*w1.y; o1.z = v1.z*scale*w1.z; o1.w = v1.w*scale*w1.w;
    float4* outr = (float4*)(out + (size_t)tok*256);
    outr[lane*2] = o0; outr[lane*2+1] = o1;
}

// C[M,N] = A[M,K]*W[N,K]^T ; tile 128x128, 256 thr, 8x8 micro
__global__ __launch_bounds__(256) void gemm128_kernel(const float* __restrict__ A,
                               const float* __restrict__ W,
                               float* __restrict__ C,
                               int M, int N, int K)
{
    __shared__ float As[16][132];
    __shared__ float Ws[16][132];
    int bm = blockIdx.y * 128;
    int bn = blockIdx.x * 128;
    int tid = threadIdx.x;
    int tx = tid & 15, ty = tid >> 4;
    float acc[8][8] = {};
    for (int k0 = 0; k0 < K; k0 += 16) {
        #pragma unroll
        for (int s = 0; s < 2; s++) {
            int q = tid + s*256;
            int r = q >> 2, c = q & 3;
            float4 v = *(const float4*)&A[(size_t)(bm+r)*K + k0 + c*4];
            As[c*4+0][r] = v.x; As[c*4+1][r] = v.y; As[c*4+2][r] = v.z; As[c*4+3][r] = v.w;
            float4 u = *(const float4*)&W[(size_t)(bn+r)*K + k0 + c*4];
            Ws[c*4+0][r] = u.x; Ws[c*4+1][r] = u.y; Ws[c*4+2][r] = u.z; Ws[c*4+3][r] = u.w;
        }
        __syncthreads();
        #pragma unroll
        for (int k = 0; k < 16; k++) {
            float4 a0 = *(const float4*)&As[k][ty*8];
            float4 a1 = *(const float4*)&As[k][ty*8+4];
            float4 b0 = *(const float4*)&Ws[k][tx*8];
            float4 b1 = *(const float4*)&Ws[k][tx*8+4];
            float a[8] = {a0.x,a0.y,a0.z,a0.w,a1.x,a1.y,a1.z,a1.w};
            float b[8] = {b0.x,b0.y,b0.z,b0.w,b1.x,b1.y,b1.z,b1.w};
            #pragma unroll
            for (int i = 0; i < 8; i++)
                #pragma unroll
                for (int j = 0; j < 8; j++)
                    acc[i][j] = fmaf(a[i], b[j], acc[i][j]);
        }
        __syncthreads();
    }
    #pragma unroll
    for (int i = 0; i < 8; i++) {
        int m = bm + ty*8 + i;
        #pragma unroll
        for (int j = 0; j < 8; j++)
            C[(size_t)m*N + bn + tx*8 + j] = acc[i][j];
    }
}

// tile 64x64, 64 thr, 8x8 micro. EPI: 0 store, 1 accumulate, 2 bias+gelu
template<int EPI>
__global__ __launch_bounds__(64) void gemm64_kernel(const float* __restrict__ A,
                              const float* __restrict__ W,
                              const float* __restrict__ bias,
                              float* __restrict__ C,
                              int M, int N, int K)
{
    __shared__ float As[16][68];
    __shared__ float Ws[16][68];
    int bm = blockIdx.y * 64;
    int bn = blockIdx.x * 64;
    int tid = threadIdx.x;
    int tx = tid & 7, ty = tid >> 3;
    float acc[8][8] = {};
    for (int k0 = 0; k0 < K; k0 += 16) {
        #pragma unroll
        for (int s = 0; s < 4; s++) {
            int q = tid + s*64;
            int r = q >> 2, c = q & 3;
            float4 v = *(const float4*)&A[(size_t)(bm+r)*K + k0 + c*4];
            As[c*4+0][r] = v.x; As[c*4+1][r] = v.y; As[c*4+2][r] = v.z; As[c*4+3][r] = v.w;
            float4 u = *(const float4*)&W[(size_t)(bn+r)*K + k0 + c*4];
            Ws[c*4+0][r] = u.x; Ws[c*4+1][r] = u.y; Ws[c*4+2][r] = u.z; Ws[c*4+3][r] = u.w;
        }
        __syncthreads();
        #pragma unroll
        for (int k = 0; k < 16; k++) {
            float4 a0 = *(const float4*)&As[k][ty*8];
            float4 a1 = *(const float4*)&As[k][ty*8+4];
            float4 b0 = *(const float4*)&Ws[k][tx*8];
            float4 b1 = *(const float4*)&Ws[k][tx*8+4];
            float a[8] = {a0.x,a0.y,a0.z,a0.w,a1.x,a1.y,a1.z,a1.w};
            float b[8] = {b0.x,b0.y,b0.z,b0.w,b1.x,b1.y,b1.z,b1.w};
            #pragma unroll
            for (int i = 0; i < 8; i++)
                #pragma unroll
                for (int j = 0; j < 8; j++)
                    acc[i][j] = fmaf(a[i], b[j], acc[i][j]);
        }
        __syncthreads();
    }
    #pragma unroll
    for (int i = 0; i < 8; i++) {
        int m = bm + ty*8 + i;
        #pragma unroll
        for (int j = 0; j < 8; j++) {
            int n = bn + tx*8 + j;
            size_t idx = (size_t)m*N + n;
            if (EPI == 0) C[idx] = acc[i][j];
            else if (EPI == 1) C[idx] += acc[i][j];
            else {
                float v = acc[i][j] + bias[n];
                float v3 = v*v*v;
                C[idx] = 0.5f * v * (1.f + tanhf(0.7978845608028654f * (v + 0.044715f*v3)));
            }
        }
    }
}

__global__ __launch_bounds__(256) void conv1d_silu_kernel(const float* __restrict__ xz,
                                   const float* __restrict__ cw,
                                   const float* __restrict__ cb,
                                   float* __restrict__ xin)
{
    int idx = blockIdx.x * blockDim.x + threadIdx.x; // BT*DI
    int token = idx >> 9;
    int e = idx & 511;
    int t = token & 255;
    float acc = cb[e];
    const float* wk = cw + e*4;
    #pragma unroll
    for (int k = 0; k < 4; k++) {
        int tt = t - 3 + k;
        if (tt >= 0)
            acc = fmaf(xz[(size_t)(token - 3 + k)*1024 + e], wk[k], acc);
    }
    xin[idx] = acc / (1.f + __expf(-acc));
}

// x_proj: dbc[64 tokens][48] per block; writes dt + interleaved (B,C)
__global__ __launch_bounds__(128) void xproj_kernel(const float* __restrict__ xin,
                             const float* __restrict__ w,
                             float* __restrict__ dt,
                             float2* __restrict__ bc)
{
    __shared__ float sx[64*65];
    __shared__ float sw[48*65];
    int tok0 = blockIdx.x * 64;
    int tid = threadIdx.x;
    int tg = tid & 15;       // 4 tokens each
    int jg = tid >> 4;       // 0..7, 6 j each
    float acc[4][6] = {};
    for (int k0 = 0; k0 < 512; k0 += 64) {
        #pragma unroll
        for (int s = 0; s < 8; s++) {
            int q = tid + s*128;           // float4 id, 0..1023
            int t = q >> 4, kq = q & 15;
            float4 v = *(const float4*)&xin[(size_t)(tok0+t)*512 + k0 + kq*4];
            float* dst = sx + t*65 + kq*4;
            dst[0]=v.x; dst[1]=v.y; dst[2]=v.z; dst[3]=v.w;
        }
        #pragma unroll
        for (int s = 0; s < 6; s++) {
            int q = tid + s*128;           // 0..767
            int r = q >> 4, kq = q & 15;
            float4 v = *(const float4*)&w[(size_t)r*512 + k0 + kq*4];
            float* dst = sw + r*65 + kq*4;
            dst[0]=v.x; dst[1]=v.y; dst[2]=v.z; dst[3]=v.w;
        }
        __syncthreads();
        #pragma unroll 4
        for (int k = 0; k < 64; k++) {
            float xv[4], wv[6];
            #pragma unroll
            for (int i = 0; i < 4; i++) xv[i] = sx[(tg*4+i)*65 + k];
            #pragma unroll
            for (int j = 0; j < 6; j++) wv[j] = sw[(jg*6+j)*65 + k];
            #pragma unroll
            for (int i = 0; i < 4; i++)
                #pragma unroll
                for (int j = 0; j < 6; j++)
                    acc[i][j] = fmaf(xv[i], wv[j], acc[i][j]);
        }
        __syncthreads();
    }
    #pragma unroll
    for (int i = 0; i < 4; i++) {
        int tok = tok0 + tg*4 + i;
        #pragma unroll
        for (int jj = 0; jj < 6; jj++) {
            int j = jg*6 + jj;
            float v = acc[i][jj];
            if (j < 16)       dt[tok*16 + j] = v;
            else if (j < 32)  bc[tok*16 + (j-16)].x = v;
            else              bc[tok*16 + (j-32)].y = v;
        }
    }
}

__global__ __launch_bounds__(256) void dtproj_kernel(const float* __restrict__ dt,
                              const float* __restrict__ dpw,
                              const float* __restrict__ dpb,
                              const float* __restrict__ xin,
                              float2* __restrict__ du)
{
    int idx = blockIdx.x * blockDim.x + threadIdx.x; // BT*DI
    int token = idx >> 9;
    int e = idx & 511;
    const float* dr = dt + token*16;
    const float* wr = dpw + e*16;
    float acc = dpb[e];
    #pragma unroll
    for (int k = 0; k < 16; k++) acc = fmaf(dr[k], wr[k], acc);
    float sp = (acc > 20.f) ? acc : log1pf(expf(acc));
    du[idx] = make_float2(sp, xin[idx]);
}

__global__ __launch_bounds__(256) void scan_kernel(const float2* __restrict__ du,
                            const float* __restrict__ xz,
                            const float2* __restrict__ bc,
                            const float* __restrict__ A_log,
                            const float* __restrict__ Dp,
                            float* __restrict__ yout)
{
    int tid = blockIdx.x * blockDim.x + threadIdx.x;
    int ch = tid >> 4;           // b*512 + e
    int n = tid & 15;
    int b = ch >> 9;
    int e = ch & 511;
    float A  = -expf(A_log[e*16 + n]);
    float Dv = Dp[e];
    float h = 0.f;
    int tok0 = b * 256;
    for (int t = 0; t < 256; t++) {
        int tok = tok0 + t;
        float2 duv = du[(size_t)tok*512 + e];       // (delta, u) broadcast
        float2 bcv = bc[tok*16 + n];                // (B, C)
        float dA = __expf(duv.x * A);
        h = fmaf(h, dA, duv.x * bcv.x * duv.y);
        float part = h * bcv.y;
        #pragma unroll
        for (int o = 8; o > 0; o >>= 1) part += __shfl_down_sync(0xffffffffu, part, o, 16);
        if (n == 0) {
            float zv = xz[(size_t)tok*1024 + 512 + e];
            float y = part + duv.y * Dv;
            yout[(size_t)tok*512 + e] = y * (zv / (1.f + __expf(-zv)));
        }
    }
}

// =====================================================================
// Head tail
// =====================================================================
__global__ __launch_bounds__(256) void head2_kernel(const float* __restrict__ hh,
                             const float* __restrict__ w,
                             const float* __restrict__ b,
                             float* __restrict__ logits)
{
    int wid = (blockIdx.x * blockDim.x + threadIdx.x) >> 5;
    int lane = threadIdx.x & 31;
    const float* xr = hh + (size_t)wid*64;
    float acc = fmaf(xr[lane], w[lane], xr[lane+32]*w[lane+32]);
    #pragma unroll
    for (int o = 16; o > 0; o >>= 1) acc += __shfl_down_sync(0xffffffffu, acc, o);
    if (lane == 0) logits[wid] = acc + b[0];
}

__global__ __launch_bounds__(256) void softmax_kernel(const float* __restrict__ logits,
                               float* __restrict__ out)
{
    int b = blockIdx.x;
    int t = threadIdx.x; // 256
    float v = logits[b*256 + t];
    __shared__ float red[8];
    __shared__ float sM, sS;
    float m = v;
    #pragma unroll
    for (int o = 16; o > 0; o >>= 1) m = fmaxf(m, __shfl_xor_sync(0xffffffffu, m, o));
    if ((t & 31) == 0) red[t >> 5] = m;
    __syncthreads();
    if (t < 8) {
        float mm = red[t];
        #pragma unroll
        for (int o = 4; o > 0; o >>= 1) mm = fmaxf(mm, __shfl_xor_sync(0xffu, mm, o, 8));
        if (t == 0) sM = mm;
    }
    __syncthreads();
    float e = expf(v - sM);
    float s = e;
    #pragma unroll
    for (int o = 16; o > 0; o >>= 1) s += __shfl_xor_sync(0xffffffffu, s, o);
    __syncthreads();
    if ((t & 31) == 0) red[t >> 5] = s;
    __syncthreads();
    if (t < 8) {
        float ss2 = red[t];
        #pragma unroll
        for (int o = 4; o > 0; o >>= 1) ss2 += __shfl_xor_sync(0xffu, ss2, o, 8);
        if (t == 0) sS = ss2;
    }
    __syncthreads();
    out[b*256 + t] = (t == 0) ? 0.f : e / sS;
}

// =====================================================================
// Launcher
// =====================================================================
extern "C" void kernel_launch(void* const* d_in, const int* in_sizes, int n_in,
                              void* d_out, int out_size)
{
    (void)in_sizes; (void)n_in; (void)out_size;
    const float* x        = (const float*)d_in[0];
    const float* cnn_w1   = (const float*)d_in[1];
    const float* cnn_b1   = (const float*)d_in[2];
    const float* cnn_w2   = (const float*)d_in[3];
    const float* cnn_b2   = (const float*)d_in[4];
    const float* cnn_w3   = (const float*)d_in[5];
    const float* cnn_b3   = (const float*)d_in[6];
    const float* fc_w     = (const float*)d_in[7];
    const float* fc_b     = (const float*)d_in[8];
    const float* norm_w   = (const float*)d_in[9];
    const float* in_proj_w= (const float*)d_in[10];
    const float* conv1d_w = (const float*)d_in[11];
    const float* conv1d_b = (const float*)d_in[12];
    const float* x_proj_w = (const float*)d_in[13];
    const float* dt_proj_w= (const float*)d_in[14];
    const float* dt_proj_b= (const float*)d_in[15];
    const float* A_log    = (const float*)d_in[16];
    const float* Dp       = (const float*)d_in[17];
    const float* out_proj_w=(const float*)d_in[18];
    const float* norm_f_w = (const float*)d_in[19];
    const float* head_w1  = (const float*)d_in[20];
    const float* head_b1  = (const float*)d_in[21];
    const float* head_w2  = (const float*)d_in[22];
    const float* head_b2  = (const float*)d_in[23];
    float* out = (float*)d_out;

    float *f1, *f2, *z1, *h, *xn, *xz, *xin, *dt, *y, *hh, *logits;
    float2 *bc, *du;
    cudaGetSymbolAddress((void**)&f1, g_f1);
    cudaGetSymbolAddress((void**)&f2, g_f2);
    cudaGetSymbolAddress((void**)&z1, g_z1);
    cudaGetSymbolAddress((void**)&h,  g_h);
    cudaGetSymbolAddress((void**)&xn, g_xn);
    cudaGetSymbolAddress((void**)&xz, g_xz);
    cudaGetSymbolAddress((void**)&xin,g_xin);
    cudaGetSymbolAddress((void**)&dt, g_dt);
    cudaGetSymbolAddress((void**)&bc, g_bc);
    cudaGetSymbolAddress((void**)&du, g_du);
    cudaGetSymbolAddress((void**)&y,  g_y);
    cudaGetSymbolAddress((void**)&hh, g_hh);
    cudaGetSymbolAddress((void**)&logits, g_logits);

    // --- CNN encoder ---
    conv1_kernel<<<2048, 512>>>(x, cnn_w1, cnn_b1, f1);
    conv2_kernel<<<dim3(2048, 4), 64>>>(f1, cnn_w2, cnn_b2, f2);
    conv3pool_kernel<<<2048, 64>>>(f2, cnn_w3, cnn_b3, z1);
    fc_kernel<<<64, 256>>>(z1, fc_w, fc_b, h);

    // --- Mamba layers ---
    for (int l = 0; l < 6; l++) {
        const float* nw  = norm_w     + (size_t)l*DM;
        const float* ipw = in_proj_w  + (size_t)l*2*DI*DM;
        const float* cw  = conv1d_w   + (size_t)l*DI*4;
        const float* cb  = conv1d_b   + (size_t)l*DI;
        const float* xpw = x_proj_w   + (size_t)l*48*DI;
        const float* dpw = dt_proj_w  + (size_t)l*DI*DTR;
        const float* dpb = dt_proj_b  + (size_t)l*DI;
        const float* al  = A_log      + (size_t)l*DI*DS;
        const float* dv  = Dp         + (size_t)l*DI;
        const float* opw = out_proj_w + (size_t)l*DM*DI;

        rmsnorm_kernel<<<256, 256>>>(h, nw, xn);
        gemm128_kernel<<<dim3(8, 16), 256>>>(xn, ipw, xz, BT, 1024, 256);
        conv1d_silu_kernel<<<BT*DI/256, 256>>>(xz, cw, cb, xin);
        xproj_kernel<<<32, 128>>>(xin, xpw, dt, bc);
        dtproj_kernel<<<BT*DI/256, 256>>>(dt, dpw, dpb, xin, du);
        scan_kernel<<<BATCH*DI*DS/256, 256>>>(du, xz, bc, al, dv, y);
        gemm64_kernel<1><<<dim3(4, 32), 64>>>(y, opw, nullptr, h, BT, 256, 512);
    }

    // --- Head ---
    rmsnorm_kernel<<<256, 256>>>(h, norm_f_w, xn);
    gemm64_kernel<2><<<dim3(1, 32), 64>>>(xn, head_w1, head_b1, hh, BT, 64, 256);
    head2_kernel<<<BT*32/256, 256>>>(hh, head_w2, head_b2, logits);
    softmax_kernel<<<BATCH, 256>>>(logits, out);
}

// round 3
// speedup vs baseline: 1.1224x; 1.1224x over previous
#include <cuda_runtime.h>
#include <math.h>

// ---- problem constants ----
#define BATCH   8
#define TT      256
#define BT      2048          // BATCH*TT
#define DM      256           // d_model
#define DI      512           // d_inner
#define DS      16            // d_state
#define DTR     16            // dt_rank

typedef unsigned long long u64;

// f32x2 packed-FMA helpers (sm_100+; FFMA2 reachable only via PTX per B300 docs)
__device__ __forceinline__ u64 pk2(float lo, float hi) {
    u64 d;
    asm("mov.b64 %0, {%1, %2};" : "=l"(d)
        : "r"(__float_as_uint(lo)), "r"(__float_as_uint(hi)));
    return d;
}
__device__ __forceinline__ u64 ffma2(u64 a, u64 b, u64 c) {
    u64 d;
    asm("fma.rn.f32x2 %0, %1, %2, %3;" : "=l"(d) : "l"(a), "l"(b), "l"(c));
    return d;
}
__device__ __forceinline__ float2 upk2(u64 v) {
    unsigned lo, hi;
    asm("mov.b64 {%0, %1}, %2;" : "=r"(lo), "=r"(hi) : "l"(v));
    return make_float2(__uint_as_float(lo), __uint_as_float(hi));
}
union F4U { float4 f; u64 u[2]; };

// ---- scratch (device globals; no allocation allowed) ----
__device__ float  g_f1[2048*16*32*32];   // conv1 out
__device__ float  g_f2[2048*32*16*16];   // conv2 out
__device__ float  g_z1[2048*32];         // pooled CNN features
__device__ float  g_h [BT*DM];           // residual stream
__device__ float  g_xn[BT*DM];           // rmsnorm output
__device__ float  g_xz[BT*2*DI];         // in_proj output (xin | z)
__device__ float  g_xin[BT*DI];          // conv1d+silu output
__device__ float  g_dt[BT*DTR];          // dt part of x_proj
__device__ float2 g_bc[BT*DS];           // (B,C) interleaved
__device__ float2 g_du[BT*DI];           // (delta, u) interleaved
__device__ float  g_y [BT*DI];           // scan output gated
__device__ float  g_hh[BT*64];           // head hidden
__device__ float  g_logits[BT];

// =====================================================================
// CNN
// =====================================================================
__global__ __launch_bounds__(512) void conv1_kernel(const float* __restrict__ x,
                             const float* __restrict__ w,
                             const float* __restrict__ b,
                             float* __restrict__ out)
{
    // x: (2048,1,64,64) -> out: (2048,16,32,32), stride2 SAME (pad hi=1), relu
    __shared__ float sin[65*65];
    __shared__ float sw[144];
    __shared__ float sb[16];
    int f = blockIdx.x;
    const float* xf = x + (size_t)f*4096;
    for (int i = threadIdx.x; i < 65*65; i += 512) {
        int r = i / 65, c = i - r*65;
        sin[i] = (r < 64 && c < 64) ? xf[r*64+c] : 0.f;
    }
    if (threadIdx.x < 144) sw[threadIdx.x] = w[threadIdx.x];
    if (threadIdx.x < 16)  sb[threadIdx.x] = b[threadIdx.x];
    __syncthreads();
    int xg = threadIdx.x & 3;            // ox group (8 outputs)
    int oy = (threadIdx.x >> 2) & 31;    // output row
    int cq = threadIdx.x >> 7;           // co quad (4 channels)
    float acc[4][8];
    #pragma unroll
    for (int c = 0; c < 4; c++) {
        float bb = sb[cq*4+c];
        #pragma unroll
        for (int q = 0; q < 8; q++) acc[c][q] = bb;
    }
    int i0 = oy*2, j0 = xg*16;
    #pragma unroll
    for (int ky = 0; ky < 3; ky++) {
        const float* rp = sin + (i0+ky)*65 + j0;
        float r[17];
        #pragma unroll
        for (int t = 0; t < 17; t++) r[t] = rp[t];
        #pragma unroll
        for (int c = 0; c < 4; c++) {
            const float* wp = sw + (cq*4+c)*9 + ky*3;
            float w0 = wp[0], w1 = wp[1], w2 = wp[2];
            #pragma unroll
            for (int q = 0; q < 8; q++)
                acc[c][q] = fmaf(r[2*q],w0, fmaf(r[2*q+1],w1, fmaf(r[2*q+2],w2, acc[c][q])));
        }
    }
    #pragma unroll
    for (int c = 0; c < 4; c++)
        #pragma unroll
        for (int q = 0; q < 8; q++)
            out[((size_t)f*16 + cq*4+c)*1024 + oy*32 + xg*8 + q] = fmaxf(acc[c][q], 0.f);
}

__global__ __launch_bounds__(256) void conv2_kernel(const float* __restrict__ in,
                             const float* __restrict__ w,
                             const float* __restrict__ b,
                             float* __restrict__ out)
{
    // in (2048,16,32,32) -> out (2048,32,16,16); full frame per block,
    // 2 passes of 8 input channels; weights in smem.
    __shared__ float sin[8*33*34];   // 35.9KB
    __shared__ float sw[2304];       // 32co * 8ci * 9 = 9.2KB
    int f = blockIdx.x;
    int tid = threadIdx.x;
    int cg  = tid >> 5;        // 0..7 -> 4 co each (warp-uniform)
    int lane = tid & 31;
    int oy = lane >> 1;        // 0..15
    int xh = lane & 1;         // 0..1 -> 8 ox each
    float acc[4][8];
    #pragma unroll
    for (int c = 0; c < 4; c++) {
        float bb = __ldg(&b[cg*4+c]);
        #pragma unroll
        for (int q = 0; q < 8; q++) acc[c][q] = bb;
    }
    #pragma unroll 1
    for (int pass = 0; pass < 2; pass++) {
        int ci0 = pass*8;
        __syncthreads();
        for (int idx = tid; idx < 8*33*33; idx += 256) {
            int ci = idx / 1089;
            int rem = idx - ci*1089;
            int i = rem / 33, j = rem - i*33;
            sin[ci*1122 + i*34 + j] = (i < 32 && j < 32)
                ? in[(size_t)f*16384 + (ci0+ci)*1024 + i*32 + j] : 0.f;
        }
        for (int idx = tid; idx < 2304; idx += 256) {
            int co = idx / 72;
            int rem = idx - co*72;
            int ci_l = rem / 9, k = rem - ci_l*9;
            sw[idx] = w[(co*16 + ci0 + ci_l)*9 + k];
        }
        __syncthreads();
        #pragma unroll 1
        for (int ci = 0; ci < 8; ci++) {
            const float* base = sin + ci*1122 + (2*oy)*34 + xh*16;
            float r0[17], r1[17], r2[17];
            #pragma unroll
            for (int t = 0; t < 17; t++) { r0[t]=base[t]; r1[t]=base[34+t]; r2[t]=base[68+t]; }
            #pragma unroll
            for (int c = 0; c < 4; c++) {
                const float* wp = sw + (cg*4+c)*72 + ci*9;
                float w0=wp[0],w1=wp[1],w2=wp[2],w3=wp[3],w4=wp[4],w5=wp[5],w6=wp[6],w7=wp[7],w8=wp[8];
                #pragma unroll
                for (int q = 0; q < 8; q++) {
                    float a = acc[c][q];
                    int j0 = 2*q;
                    a = fmaf(r0[j0],w0,a); a = fmaf(r0[j0+1],w1,a); a = fmaf(r0[j0+2],w2,a);
                    a = fmaf(r1[j0],w3,a); a = fmaf(r1[j0+1],w4,a); a = fmaf(r1[j0+2],w5,a);
                    a = fmaf(r2[j0],w6,a); a = fmaf(r2[j0+1],w7,a); a = fmaf(r2[j0+2],w8,a);
                    acc[c][q] = a;
                }
            }
        }
    }
    #pragma unroll
    for (int c = 0; c < 4; c++)
        #pragma unroll
        for (int q = 0; q < 8; q++)
            out[((size_t)f*32 + cg*4+c)*256 + oy*16 + xh*8 + q] = fmaxf(acc[c][q], 0.f);
}

__global__ __launch_bounds__(256) void conv3pool_kernel(const float* __restrict__ in,
                                 const float* __restrict__ w,
                                 const float* __restrict__ b,
                                 float* __restrict__ z1)
{
    // in (2048,32,16,16) -> conv (32,8,8) relu -> mean -> z1 (2048,32)
    // 2 frames per block; 4 passes of 8 ci
    __shared__ float sin[2*8*17*18];  // 19.6KB
    __shared__ float sw[32*8*9];      // 9.2KB
    int f0 = blockIdx.x * 2;
    int tid = threadIdx.x;
    int fr = tid >> 7;          // frame 0/1
    int t  = tid & 127;
    int cg = t >> 4;            // 0..7 -> 4 co
    int oy = (t >> 1) & 7;      // 0..7
    int xh = t & 1;             // 0..1 -> 4 ox each
    float acc[4][4];
    #pragma unroll
    for (int c = 0; c < 4; c++) {
        float bb = __ldg(&b[cg*4+c]);
        #pragma unroll
        for (int q = 0; q < 4; q++) acc[c][q] = bb;
    }
    #pragma unroll 1
    for (int pass = 0; pass < 4; pass++) {
        int ci0 = pass*8;
        __syncthreads();
        for (int idx = tid; idx < 2*8*17*17; idx += 256) {
            int fr2 = idx / 2312;
            int rem = idx - fr2*2312;
            int ci = rem / 289;
            int r2 = rem - ci*289;
            int i = r2 / 17, j = r2 - i*17;
            sin[fr2*2448 + ci*306 + i*18 + j] = (i < 16 && j < 16)
                ? in[(size_t)(f0+fr2)*8192 + (ci0+ci)*256 + i*16 + j] : 0.f;
        }
        for (int idx = tid; idx < 2304; idx += 256) {
            int co = idx / 72;
            int rem = idx - co*72;
            int ci_l = rem / 9, k = rem - ci_l*9;
            sw[idx] = w[(co*32 + ci0 + ci_l)*9 + k];
        }
        __syncthreads();
        #pragma unroll 1
        for (int ci = 0; ci < 8; ci++) {
            const float* base = sin + fr*2448 + ci*306 + (2*oy)*18 + xh*8;
            float r0[9], r1[9], r2[9];
            #pragma unroll
            for (int q = 0; q < 9; q++) { r0[q]=base[q]; r1[q]=base[18+q]; r2[q]=base[36+q]; }
            #pragma unroll
            for (int c = 0; c < 4; c++) {
                const float* wp = sw + (cg*4+c)*72 + ci*9;
                float w0=wp[0],w1=wp[1],w2=wp[2],w3=wp[3],w4=wp[4],w5=wp[5],w6=wp[6],w7=wp[7],w8=wp[8];
                #pragma unroll
                for (int q = 0; q < 4; q++) {
                    float a = acc[c][q];
                    int j0 = 2*q;
                    a = fmaf(r0[j0],w0,a); a = fmaf(r0[j0+1],w1,a); a = fmaf(r0[j0+2],w2,a);
                    a = fmaf(r1[j0],w3,a); a = fmaf(r1[j0+1],w4,a); a = fmaf(r1[j0+2],w5,a);
                    a = fmaf(r2[j0],w6,a); a = fmaf(r2[j0+1],w7,a); a = fmaf(r2[j0+2],w8,a);
                    acc[c][q] = a;
                }
            }
        }
    }
    #pragma unroll
    for (int c = 0; c < 4; c++) {
        float s = 0.f;
        #pragma unroll
        for (int q = 0; q < 4; q++) s += fmaxf(acc[c][q], 0.f);
        // reduce over 16 lanes (oy*2+xh) of this (fr,cg) group
        #pragma unroll
        for (int o = 8; o > 0; o >>= 1) s += __shfl_down_sync(0xffffffffu, s, o, 16);
        if (oy == 0 && xh == 0) z1[(f0+fr)*32 + cg*4 + c] = s * (1.f/64.f);
    }
}

__global__ __launch_bounds__(256) void fc_kernel(const float* __restrict__ z1,
                          const float* __restrict__ w,
                          const float* __restrict__ b,
                          float* __restrict__ h)
{
    __shared__ float sz[32*33];
    int tok0 = blockIdx.x * 32;
    int j = threadIdx.x;
    for (int idx = threadIdx.x; idx < 1024; idx += 256) {
        int t = idx >> 5, k = idx & 31;
        sz[t*33 + k] = z1[(tok0+t)*32 + k];
    }
    __syncthreads();
    float wr[32];
    #pragma unroll
    for (int k = 0; k < 32; k++) wr[k] = w[j*32 + k];
    float bb = b[j];
    for (int t = 0; t < 32; t++) {
        float acc = bb;
        const float* zr = sz + t*33;
        #pragma unroll
        for (int k = 0; k < 32; k++) acc = fmaf(zr[k], wr[k], acc);
        h[(size_t)(tok0+t)*256 + j] = acc;
    }
}

// =====================================================================
// Mamba pieces
// =====================================================================
__global__ __launch_bounds__(256) void rmsnorm_kernel(const float* __restrict__ x,
                               const float* __restrict__ w,
                               float* __restrict__ out)
{
    int tok = blockIdx.x*8 + (threadIdx.x >> 5);
    int lane = threadIdx.x & 31;
    const float4* xr = (const float4*)(x + (size_t)tok*256);
    float4 v0 = xr[lane*2], v1 = xr[lane*2+1];
    float ss = v0.x*v0.x + v0.y*v0.y + v0.z*v0.z + v0.w*v0.w
             + v1.x*v1.x + v1.y*v1.y + v1.z*v1.z + v1.w*v1.w;
    #pragma unroll
    for (int o = 16; o > 0; o >>= 1) ss += __shfl_xor_sync(0xffffffffu, ss, o);
    float scale = rsqrtf(ss * (1.f/256.f) + 1e-5f);
    const float4* wr = (const float4*)w;
    float4 w0 = wr[lane*2], w1 = wr[lane*2+1];
    float4 o0, o1;
    o0.x = v0.x*scale*w0.x; o0.y = v0.y*scale*w0.y; o0.z = v0.z*scale*w0.z; o0.w = v0.w*scale*w0.w;
    o1.x = v1.x*scale*w1.x; o1.y = v1.y*scale*w1.y; o1.z = v1.z*scale*w1.z; o1.w = v1.w*scale*w1.w;
    float4* outr = (float4*)(out + (size_t)tok*256);
    outr[lane*2] = o0; outr[lane*2+1] = o1;
}

// C[M,N] = A[M,K]*W[N,K]^T ; tile 128x128, 256 thr, 8x8 micro, f32x2
__global__ __launch_bounds__(256) void gemm128_kernel(const float* __restrict__ A,
                               const float* __restrict__ W,
                               float* __restrict__ C,
                               int M, int N, int K)
{
    __shared__ float As[16][132];
    __shared__ float Ws[16][132];
    int bm = blockIdx.y * 128;
    int bn = blockIdx.x * 128;
    int tid = threadIdx.x;
    int tx = tid & 15, ty = tid >> 4;
    u64 acc[8][4];
    #pragma unroll
    for (int i = 0; i < 8; i++)
        #pragma unroll
        for (int j = 0; j < 4; j++) acc[i][j] = 0ull;
    for (int k0 = 0; k0 < K; k0 += 16) {
        #pragma unroll
        for (int s = 0; s < 2; s++) {
            int q = tid + s*256;
            int r = q >> 2, c = q & 3;
            float4 v = *(const float4*)&A[(size_t)(bm+r)*K + k0 + c*4];
            As[c*4+0][r] = v.x; As[c*4+1][r] = v.y; As[c*4+2][r] = v.z; As[c*4+3][r] = v.w;
            float4 u = *(const float4*)&W[(size_t)(bn+r)*K + k0 + c*4];
            Ws[c*4+0][r] = u.x; Ws[c*4+1][r] = u.y; Ws[c*4+2][r] = u.z; Ws[c*4+3][r] = u.w;
        }
        __syncthreads();
        #pragma unroll
        for (int k = 0; k < 16; k++) {
            float4 a0 = *(const float4*)&As[k][ty*8];
            float4 a1 = *(const float4*)&As[k][ty*8+4];
            F4U b0, b1;
            b0.f = *(const float4*)&Ws[k][tx*8];
            b1.f = *(const float4*)&Ws[k][tx*8+4];
            u64 bp[4] = { b0.u[0], b0.u[1], b1.u[0], b1.u[1] };
            float av[8] = {a0.x,a0.y,a0.z,a0.w,a1.x,a1.y,a1.z,a1.w};
            #pragma unroll
            for (int i = 0; i < 8; i++) {
                u64 ad = pk2(av[i], av[i]);
                #pragma unroll
                for (int j = 0; j < 4; j++)
                    acc[i][j] = ffma2(ad, bp[j], acc[i][j]);
            }
        }
        __syncthreads();
    }
    #pragma unroll
    for (int i = 0; i < 8; i++) {
        int m = bm + ty*8 + i;
        float2 v0 = upk2(acc[i][0]), v1 = upk2(acc[i][1]);
        float2 v2 = upk2(acc[i][2]), v3 = upk2(acc[i][3]);
        float4 o0 = make_float4(v0.x, v0.y, v1.x, v1.y);
        float4 o1 = make_float4(v2.x, v2.y, v3.x, v3.y);
        *(float4*)&C[(size_t)m*N + bn + tx*8]     = o0;
        *(float4*)&C[(size_t)m*N + bn + tx*8 + 4] = o1;
    }
}

// tile 64x64, 256 thr, 4x4 micro, f32x2. EPI: 1 accumulate, 2 bias+gelu
template<int EPI>
__global__ __launch_bounds__(256) void gemm64_kernel(const float* __restrict__ A,
                              const float* __restrict__ W,
                              const float* __restrict__ bias,
                              float* __restrict__ C,
                              int M, int N, int K)
{
    __shared__ float As[16][68];
    __shared__ float Ws[16][68];
    int bm = blockIdx.y * 64;
    int bn = blockIdx.x * 64;
    int tid = threadIdx.x;
    int tx = tid & 15, ty = tid >> 4;
    u64 acc[4][2];
    #pragma unroll
    for (int i = 0; i < 4; i++) { acc[i][0] = 0ull; acc[i][1] = 0ull; }
    for (int k0 = 0; k0 < K; k0 += 16) {
        {
            int r = tid >> 2, c = tid & 3;
            float4 v = *(const float4*)&A[(size_t)(bm+r)*K + k0 + c*4];
            As[c*4+0][r] = v.x; As[c*4+1][r] = v.y; As[c*4+2][r] = v.z; As[c*4+3][r] = v.w;
            float4 u = *(const float4*)&W[(size_t)(bn+r)*K + k0 + c*4];
            Ws[c*4+0][r] = u.x; Ws[c*4+1][r] = u.y; Ws[c*4+2][r] = u.z; Ws[c*4+3][r] = u.w;
        }
        __syncthreads();
        #pragma unroll
        for (int k = 0; k < 16; k++) {
            float4 a0 = *(const float4*)&As[k][ty*4];
            F4U b0;
            b0.f = *(const float4*)&Ws[k][tx*4];
            u64 bp0 = b0.u[0], bp1 = b0.u[1];
            float av[4] = {a0.x, a0.y, a0.z, a0.w};
            #pragma unroll
            for (int i = 0; i < 4; i++) {
                u64 ad = pk2(av[i], av[i]);
                acc[i][0] = ffma2(ad, bp0, acc[i][0]);
                acc[i][1] = ffma2(ad, bp1, acc[i][1]);
            }
        }
        __syncthreads();
    }
    #pragma unroll
    for (int i = 0; i < 4; i++) {
        int m = bm + ty*4 + i;
        float2 v0 = upk2(acc[i][0]), v1 = upk2(acc[i][1]);
        float vals[4] = {v0.x, v0.y, v1.x, v1.y};
        #pragma unroll
        for (int j = 0; j < 4; j++) {
            int n = bn + tx*4 + j;
            size_t idx = (size_t)m*N + n;
            if (EPI == 1) C[idx] += vals[j];
            else {
                float v = vals[j] + bias[n];
                float v3 = v*v*v;
                C[idx] = 0.5f * v * (1.f + tanhf(0.7978845608028654f * (v + 0.044715f*v3)));
            }
        }
    }
}

__global__ __launch_bounds__(256) void conv1d_silu_kernel(const float* __restrict__ xz,
                                   const float* __restrict__ cw,
                                   const float* __restrict__ cb,
                                   float* __restrict__ xin)
{
    int idx = blockIdx.x * blockDim.x + threadIdx.x; // BT*DI
    int token = idx >> 9;
    int e = idx & 511;
    int t = token & 255;
    float acc = cb[e];
    const float* wk = cw + e*4;
    #pragma unroll
    for (int k = 0; k < 4; k++) {
        int tt = t - 3 + k;
        if (tt >= 0)
            acc = fmaf(xz[(size_t)(token - 3 + k)*1024 + e], wk[k], acc);
    }
    xin[idx] = acc / (1.f + __expf(-acc));
}

// x_proj: dbc[64 tokens][48] per block; writes dt + interleaved (B,C)
__global__ __launch_bounds__(128) void xproj_kernel(const float* __restrict__ xin,
                             const float* __restrict__ w,
                             float* __restrict__ dt,
                             float2* __restrict__ bc)
{
    __shared__ float sx[64*65];
    __shared__ float sw[48*65];
    int tok0 = blockIdx.x * 64;
    int tid = threadIdx.x;
    int tg = tid & 15;       // 4 tokens each
    int jg = tid >> 4;       // 0..7, 6 j each
    float acc[4][6] = {};
    for (int k0 = 0; k0 < 512; k0 += 64) {
        #pragma unroll
        for (int s = 0; s < 8; s++) {
            int q = tid + s*128;
            int t = q >> 4, kq = q & 15;
            float4 v = *(const float4*)&xin[(size_t)(tok0+t)*512 + k0 + kq*4];
            float* dst = sx + t*65 + kq*4;
            dst[0]=v.x; dst[1]=v.y; dst[2]=v.z; dst[3]=v.w;
        }
        #pragma unroll
        for (int s = 0; s < 6; s++) {
            int q = tid + s*128;
            int r = q >> 4, kq = q & 15;
            float4 v = *(const float4*)&w[(size_t)r*512 + k0 + kq*4];
            float* dst = sw + r*65 + kq*4;
            dst[0]=v.x; dst[1]=v.y; dst[2]=v.z; dst[3]=v.w;
        }
        __syncthreads();
        #pragma unroll 4
        for (int k = 0; k < 64; k++) {
            float xv[4], wv[6];
            #pragma unroll
            for (int i = 0; i < 4; i++) xv[i] = sx[(tg*4+i)*65 + k];
            #pragma unroll
            for (int j = 0; j < 6; j++) wv[j] = sw[(jg*6+j)*65 + k];
            #pragma unroll
            for (int i = 0; i < 4; i++)
                #pragma unroll
                for (int j = 0; j < 6; j++)
                    acc[i][j] = fmaf(xv[i], wv[j], acc[i][j]);
        }
        __syncthreads();
    }
    #pragma unroll
    for (int i = 0; i < 4; i++) {
        int tok = tok0 + tg*4 + i;
        #pragma unroll
        for (int jj = 0; jj < 6; jj++) {
            int j = jg*6 + jj;
            float v = acc[i][jj];
            if (j < 16)       dt[tok*16 + j] = v;
            else if (j < 32)  bc[tok*16 + (j-16)].x = v;
            else              bc[tok*16 + (j-32)].y = v;
        }
    }
}

__global__ __launch_bounds__(256) void dtproj_kernel(const float* __restrict__ dt,
                              const float* __restrict__ dpw,
                              const float* __restrict__ dpb,
                              const float* __restrict__ xin,
                              float2* __restrict__ du)
{
    int idx = blockIdx.x * blockDim.x + threadIdx.x; // BT*DI
    int token = idx >> 9;
    int e = idx & 511;
    const float* dr = dt + token*16;
    const float* wr = dpw + e*16;
    float acc = dpb[e];
    #pragma unroll
    for (int k = 0; k < 16; k++) acc = fmaf(dr[k], wr[k], acc);
    float sp = (acc > 20.f) ? acc : log1pf(expf(acc));
    du[idx] = make_float2(sp, xin[idx]);
}

__global__ __launch_bounds__(256) void scan_kernel(const float2* __restrict__ du,
                            const float* __restrict__ xz,
                            const float2* __restrict__ bc,
                            const float* __restrict__ A_log,
                            const float* __restrict__ Dp,
                            float* __restrict__ yout)
{
    int tid = blockIdx.x * blockDim.x + threadIdx.x;
    int ch = tid >> 4;           // b*512 + e
    int n = tid & 15;
    int b = ch >> 9;
    int e = ch & 511;
    float A  = -expf(A_log[e*16 + n]);
    float Dv = Dp[e];
    float h = 0.f;
    int tok0 = b * 256;
    for (int t = 0; t < 256; t++) {
        int tok = tok0 + t;
        float2 duv = du[(size_t)tok*512 + e];
        float2 bcv = bc[tok*16 + n];
        float dA = __expf(duv.x * A);
        h = fmaf(h, dA, duv.x * bcv.x * duv.y);
        float part = h * bcv.y;
        #pragma unroll
        for (int o = 8; o > 0; o >>= 1) part += __shfl_down_sync(0xffffffffu, part, o, 16);
        if (n == 0) {
            float zv = xz[(size_t)tok*1024 + 512 + e];
            float y = part + duv.y * Dv;
            yout[(size_t)tok*512 + e] = y * (zv / (1.f + __expf(-zv)));
        }
    }
}

// =====================================================================
// Head tail
// =====================================================================
__global__ __launch_bounds__(256) void head2_kernel(const float* __restrict__ hh,
                             const float* __restrict__ w,
                             const float* __restrict__ b,
                             float* __restrict__ logits)
{
    int wid = (blockIdx.x * blockDim.x + threadIdx.x) >> 5;
    int lane = threadIdx.x & 31;
    const float* xr = hh + (size_t)wid*64;
    float acc = fmaf(xr[lane], w[lane], xr[lane+32]*w[lane+32]);
    #pragma unroll
    for (int o = 16; o > 0; o >>= 1) acc += __shfl_down_sync(0xffffffffu, acc, o);
    if (lane == 0) logits[wid] = acc + b[0];
}

__global__ __launch_bounds__(256) void softmax_kernel(const float* __restrict__ logits,
                               float* __restrict__ out)
{
    int b = blockIdx.x;
    int t = threadIdx.x; // 256
    float v = logits[b*256 + t];
    __shared__ float red[8];
    __shared__ float sM, sS;
    float m = v;
    #pragma unroll
    for (int o = 16; o > 0; o >>= 1) m = fmaxf(m, __shfl_xor_sync(0xffffffffu, m, o));
    if ((t & 31) == 0) red[t >> 5] = m;
    __syncthreads();
    if (t < 8) {
        float mm = red[t];
        #pragma unroll
        for (int o = 4; o > 0; o >>= 1) mm = fmaxf(mm, __shfl_xor_sync(0xffu, mm, o, 8));
        if (t == 0) sM = mm;
    }
    __syncthreads();
    float e = expf(v - sM);
    float s = e;
    #pragma unroll
    for (int o = 16; o > 0; o >>= 1) s += __shfl_xor_sync(0xffffffffu, s, o);
    __syncthreads();
    if ((t & 31) == 0) red[t >> 5] = s;
    __syncthreads();
    if (t < 8) {
        float ss2 = red[t];
        #pragma unroll
        for (int o = 4; o > 0; o >>= 1) ss2 += __shfl_xor_sync(0xffu, ss2, o, 8);
        if (t == 0) sS = ss2;
    }
    __syncthreads();
    out[b*256 + t] = (t == 0) ? 0.f : e / sS;
}

// =====================================================================
// Launcher
// =====================================================================
extern "C" void kernel_launch(void* const* d_in, const int* in_sizes, int n_in,
                              void* d_out, int out_size)
{
    (void)in_sizes; (void)n_in; (void)out_size;
    const float* x        = (const float*)d_in[0];
    const float* cnn_w1   = (const float*)d_in[1];
    const float* cnn_b1   = (const float*)d_in[2];
    const float* cnn_w2   = (const float*)d_in[3];
    const float* cnn_b2   = (const float*)d_in[4];
    const float* cnn_w3   = (const float*)d_in[5];
    const float* cnn_b3   = (const float*)d_in[6];
    const float* fc_w     = (const float*)d_in[7];
    const float* fc_b     = (const float*)d_in[8];
    const float* norm_w   = (const float*)d_in[9];
    const float* in_proj_w= (const float*)d_in[10];
    const float* conv1d_w = (const float*)d_in[11];
    const float* conv1d_b = (const float*)d_in[12];
    const float* x_proj_w = (const float*)d_in[13];
    const float* dt_proj_w= (const float*)d_in[14];
    const float* dt_proj_b= (const float*)d_in[15];
    const float* A_log    = (const float*)d_in[16];
    const float* Dp       = (const float*)d_in[17];
    const float* out_proj_w=(const float*)d_in[18];
    const float* norm_f_w = (const float*)d_in[19];
    const float* head_w1  = (const float*)d_in[20];
    const float* head_b1  = (const float*)d_in[21];
    const float* head_w2  = (const float*)d_in[22];
    const float* head_b2  = (const float*)d_in[23];
    float* out = (float*)d_out;

    float *f1, *f2, *z1, *h, *xn, *xz, *xin, *dt, *y, *hh, *logits;
    float2 *bc, *du;
    cudaGetSymbolAddress((void**)&f1, g_f1);
    cudaGetSymbolAddress((void**)&f2, g_f2);
    cudaGetSymbolAddress((void**)&z1, g_z1);
    cudaGetSymbolAddress((void**)&h,  g_h);
    cudaGetSymbolAddress((void**)&xn, g_xn);
    cudaGetSymbolAddress((void**)&xz, g_xz);
    cudaGetSymbolAddress((void**)&xin,g_xin);
    cudaGetSymbolAddress((void**)&dt, g_dt);
    cudaGetSymbolAddress((void**)&bc, g_bc);
    cudaGetSymbolAddress((void**)&du, g_du);
    cudaGetSymbolAddress((void**)&y,  g_y);
    cudaGetSymbolAddress((void**)&hh, g_hh);
    cudaGetSymbolAddress((void**)&logits, g_logits);

    // --- CNN encoder ---
    conv1_kernel<<<2048, 512>>>(x, cnn_w1, cnn_b1, f1);
    conv2_kernel<<<2048, 256>>>(f1, cnn_w2, cnn_b2, f2);
    conv3pool_kernel<<<1024, 256>>>(f2, cnn_w3, cnn_b3, z1);
    fc_kernel<<<64, 256>>>(z1, fc_w, fc_b, h);

    // --- Mamba layers ---
    for (int l = 0; l < 6; l++) {
        const float* nw  = norm_w     + (size_t)l*DM;
        const float* ipw = in_proj_w  + (size_t)l*2*DI*DM;
        const float* cw  = conv1d_w   + (size_t)l*DI*4;
        const float* cb  = conv1d_b   + (size_t)l*DI;
        const float* xpw = x_proj_w   + (size_t)l*48*DI;
        const float* dpw = dt_proj_w  + (size_t)l*DI*DTR;
        const float* dpb = dt_proj_b  + (size_t)l*DI;
        const float* al  = A_log      + (size_t)l*DI*DS;
        const float* dv  = Dp         + (size_t)l*DI;
        const float* opw = out_proj_w + (size_t)l*DM*DI;

        rmsnorm_kernel<<<256, 256>>>(h, nw, xn);
        gemm128_kernel<<<dim3(8, 16), 256>>>(xn, ipw, xz, BT, 1024, 256);
        conv1d_silu_kernel<<<BT*DI/256, 256>>>(xz, cw, cb, xin);
        xproj_kernel<<<32, 128>>>(xin, xpw, dt, bc);
        dtproj_kernel<<<BT*DI/256, 256>>>(dt, dpw, dpb, xin, du);
        scan_kernel<<<BATCH*DI*DS/256, 256>>>(du, xz, bc, al, dv, y);
        gemm64_kernel<1><<<dim3(4, 32), 256>>>(y, opw, nullptr, h, BT, 256, 512);
    }

    // --- Head ---
    rmsnorm_kernel<<<256, 256>>>(h, norm_f_w, xn);
    gemm64_kernel<2><<<dim3(1, 32), 256>>>(xn, head_w1, head_b1, hh, BT, 64, 256);
    head2_kernel<<<BT*32/256, 256>>>(hh, head_w2, head_b2, logits);
    softmax_kernel<<<BATCH, 256>>>(logits, out);
}

// round 4
// speedup vs baseline: 1.2420x; 1.1065x over previous
#include <cuda_runtime.h>
#include <math.h>

// ---- problem constants ----
#define BATCH   8
#define TT      256
#define BT      2048          // BATCH*TT
#define DM      256           // d_model
#define DI      512           // d_inner
#define DS      16            // d_state
#define DTR     16            // dt_rank

typedef unsigned long long u64;

__device__ __forceinline__ u64 pk2(float lo, float hi) {
    u64 d;
    asm("mov.b64 %0, {%1, %2};" : "=l"(d)
        : "r"(__float_as_uint(lo)), "r"(__float_as_uint(hi)));
    return d;
}
__device__ __forceinline__ u64 ffma2(u64 a, u64 b, u64 c) {
    u64 d;
    asm("fma.rn.f32x2 %0, %1, %2, %3;" : "=l"(d) : "l"(a), "l"(b), "l"(c));
    return d;
}
__device__ __forceinline__ float2 upk2(u64 v) {
    unsigned lo, hi;
    asm("mov.b64 {%0, %1}, %2;" : "=r"(lo), "=r"(hi) : "l"(v));
    return make_float2(__uint_as_float(lo), __uint_as_float(hi));
}
union F4U { float4 f; u64 u[2]; };

// ---- scratch ----
__device__ float  g_f1[2048*16*32*32];
__device__ float  g_f2[2048*32*16*16];
__device__ float  g_z1[2048*32];
__device__ float  g_h [BT*DM];
__device__ float  g_xn[BT*DM];
__device__ float  g_xz[BT*2*DI];
__device__ float  g_xin[BT*DI];
__device__ float2 g_bc[BT*DS];
__device__ float2 g_du[BT*DI];
__device__ float  g_y [BT*DI];
__device__ float  g_hh[BT*64];
__device__ float  g_logits[BT];

// =====================================================================
// CNN (unchanged from round 3)
// =====================================================================
__global__ __launch_bounds__(512) void conv1_kernel(const float* __restrict__ x,
                             const float* __restrict__ w,
                             const float* __restrict__ b,
                             float* __restrict__ out)
{
    __shared__ float sin[65*65];
    __shared__ float sw[144];
    __shared__ float sb[16];
    int f = blockIdx.x;
    const float* xf = x + (size_t)f*4096;
    for (int i = threadIdx.x; i < 65*65; i += 512) {
        int r = i / 65, c = i - r*65;
        sin[i] = (r < 64 && c < 64) ? xf[r*64+c] : 0.f;
    }
    if (threadIdx.x < 144) sw[threadIdx.x] = w[threadIdx.x];
    if (threadIdx.x < 16)  sb[threadIdx.x] = b[threadIdx.x];
    __syncthreads();
    int xg = threadIdx.x & 3;
    int oy = (threadIdx.x >> 2) & 31;
    int cq = threadIdx.x >> 7;
    float acc[4][8];
    #pragma unroll
    for (int c = 0; c < 4; c++) {
        float bb = sb[cq*4+c];
        #pragma unroll
        for (int q = 0; q < 8; q++) acc[c][q] = bb;
    }
    int i0 = oy*2, j0 = xg*16;
    #pragma unroll
    for (int ky = 0; ky < 3; ky++) {
        const float* rp = sin + (i0+ky)*65 + j0;
        float r[17];
        #pragma unroll
        for (int t = 0; t < 17; t++) r[t] = rp[t];
        #pragma unroll
        for (int c = 0; c < 4; c++) {
            const float* wp = sw + (cq*4+c)*9 + ky*3;
            float w0 = wp[0], w1 = wp[1], w2 = wp[2];
            #pragma unroll
            for (int q = 0; q < 8; q++)
                acc[c][q] = fmaf(r[2*q],w0, fmaf(r[2*q+1],w1, fmaf(r[2*q+2],w2, acc[c][q])));
        }
    }
    #pragma unroll
    for (int c = 0; c < 4; c++)
        #pragma unroll
        for (int q = 0; q < 8; q++)
            out[((size_t)f*16 + cq*4+c)*1024 + oy*32 + xg*8 + q] = fmaxf(acc[c][q], 0.f);
}

__global__ __launch_bounds__(256) void conv2_kernel(const float* __restrict__ in,
                             const float* __restrict__ w,
                             const float* __restrict__ b,
                             float* __restrict__ out)
{
    __shared__ float sin[8*33*34];
    __shared__ float sw[2304];
    int f = blockIdx.x;
    int tid = threadIdx.x;
    int cg  = tid >> 5;
    int lane = tid & 31;
    int oy = lane >> 1;
    int xh = lane & 1;
    float acc[4][8];
    #pragma unroll
    for (int c = 0; c < 4; c++) {
        float bb = __ldg(&b[cg*4+c]);
        #pragma unroll
        for (int q = 0; q < 8; q++) acc[c][q] = bb;
    }
    #pragma unroll 1
    for (int pass = 0; pass < 2; pass++) {
        int ci0 = pass*8;
        __syncthreads();
        for (int idx = tid; idx < 8*33*33; idx += 256) {
            int ci = idx / 1089;
            int rem = idx - ci*1089;
            int i = rem / 33, j = rem - i*33;
            sin[ci*1122 + i*34 + j] = (i < 32 && j < 32)
                ? in[(size_t)f*16384 + (ci0+ci)*1024 + i*32 + j] : 0.f;
        }
        for (int idx = tid; idx < 2304; idx += 256) {
            int co = idx / 72;
            int rem = idx - co*72;
            int ci_l = rem / 9, k = rem - ci_l*9;
            sw[idx] = w[(co*16 + ci0 + ci_l)*9 + k];
        }
        __syncthreads();
        #pragma unroll 1
        for (int ci = 0; ci < 8; ci++) {
            const float* base = sin + ci*1122 + (2*oy)*34 + xh*16;
            float r0[17], r1[17], r2[17];
            #pragma unroll
            for (int t = 0; t < 17; t++) { r0[t]=base[t]; r1[t]=base[34+t]; r2[t]=base[68+t]; }
            #pragma unroll
            for (int c = 0; c < 4; c++) {
                const float* wp = sw + (cg*4+c)*72 + ci*9;
                float w0=wp[0],w1=wp[1],w2=wp[2],w3=wp[3],w4=wp[4],w5=wp[5],w6=wp[6],w7=wp[7],w8=wp[8];
                #pragma unroll
                for (int q = 0; q < 8; q++) {
                    float a = acc[c][q];
                    int j0 = 2*q;
                    a = fmaf(r0[j0],w0,a); a = fmaf(r0[j0+1],w1,a); a = fmaf(r0[j0+2],w2,a);
                    a = fmaf(r1[j0],w3,a); a = fmaf(r1[j0+1],w4,a); a = fmaf(r1[j0+2],w5,a);
                    a = fmaf(r2[j0],w6,a); a = fmaf(r2[j0+1],w7,a); a = fmaf(r2[j0+2],w8,a);
                    acc[c][q] = a;
                }
            }
        }
    }
    #pragma unroll
    for (int c = 0; c < 4; c++)
        #pragma unroll
        for (int q = 0; q < 8; q++)
            out[((size_t)f*32 + cg*4+c)*256 + oy*16 + xh*8 + q] = fmaxf(acc[c][q], 0.f);
}

__global__ __launch_bounds__(256) void conv3pool_kernel(const float* __restrict__ in,
                                 const float* __restrict__ w,
                                 const float* __restrict__ b,
                                 float* __restrict__ z1)
{
    __shared__ float sin[2*8*17*18];
    __shared__ float sw[32*8*9];
    int f0 = blockIdx.x * 2;
    int tid = threadIdx.x;
    int fr = tid >> 7;
    int t  = tid & 127;
    int cg = t >> 4;
    int oy = (t >> 1) & 7;
    int xh = t & 1;
    float acc[4][4];
    #pragma unroll
    for (int c = 0; c < 4; c++) {
        float bb = __ldg(&b[cg*4+c]);
        #pragma unroll
        for (int q = 0; q < 4; q++) acc[c][q] = bb;
    }
    #pragma unroll 1
    for (int pass = 0; pass < 4; pass++) {
        int ci0 = pass*8;
        __syncthreads();
        for (int idx = tid; idx < 2*8*17*17; idx += 256) {
            int fr2 = idx / 2312;
            int rem = idx - fr2*2312;
            int ci = rem / 289;
            int r2 = rem - ci*289;
            int i = r2 / 17, j = r2 - i*17;
            sin[fr2*2448 + ci*306 + i*18 + j] = (i < 16 && j < 16)
                ? in[(size_t)(f0+fr2)*8192 + (ci0+ci)*256 + i*16 + j] : 0.f;
        }
        for (int idx = tid; idx < 2304; idx += 256) {
            int co = idx / 72;
            int rem = idx - co*72;
            int ci_l = rem / 9, k = rem - ci_l*9;
            sw[idx] = w[(co*32 + ci0 + ci_l)*9 + k];
        }
        __syncthreads();
        #pragma unroll 1
        for (int ci = 0; ci < 8; ci++) {
            const float* base = sin + fr*2448 + ci*306 + (2*oy)*18 + xh*8;
            float r0[9], r1[9], r2[9];
            #pragma unroll
            for (int q = 0; q < 9; q++) { r0[q]=base[q]; r1[q]=base[18+q]; r2[q]=base[36+q]; }
            #pragma unroll
            for (int c = 0; c < 4; c++) {
                const float* wp = sw + (cg*4+c)*72 + ci*9;
                float w0=wp[0],w1=wp[1],w2=wp[2],w3=wp[3],w4=wp[4],w5=wp[5],w6=wp[6],w7=wp[7],w8=wp[8];
                #pragma unroll
                for (int q = 0; q < 4; q++) {
                    float a = acc[c][q];
                    int j0 = 2*q;
                    a = fmaf(r0[j0],w0,a); a = fmaf(r0[j0+1],w1,a); a = fmaf(r0[j0+2],w2,a);
                    a = fmaf(r1[j0],w3,a); a = fmaf(r1[j0+1],w4,a); a = fmaf(r1[j0+2],w5,a);
                    a = fmaf(r2[j0],w6,a); a = fmaf(r2[j0+1],w7,a); a = fmaf(r2[j0+2],w8,a);
                    acc[c][q] = a;
                }
            }
        }
    }
    #pragma unroll
    for (int c = 0; c < 4; c++) {
        float s = 0.f;
        #pragma unroll
        for (int q = 0; q < 4; q++) s += fmaxf(acc[c][q], 0.f);
        #pragma unroll
        for (int o = 8; o > 0; o >>= 1) s += __shfl_down_sync(0xffffffffu, s, o, 16);
        if (oy == 0 && xh == 0) z1[(f0+fr)*32 + cg*4 + c] = s * (1.f/64.f);
    }
}

__global__ __launch_bounds__(256) void fc_kernel(const float* __restrict__ z1,
                          const float* __restrict__ w,
                          const float* __restrict__ b,
                          float* __restrict__ h)
{
    // 16 tokens per block, 128 blocks
    __shared__ float sz[16*33];
    int tok0 = blockIdx.x * 16;
    int j = threadIdx.x;
    for (int idx = threadIdx.x; idx < 512; idx += 256) {
        int t = idx >> 5, k = idx & 31;
        sz[t*33 + k] = z1[(tok0+t)*32 + k];
    }
    __syncthreads();
    float wr[32];
    #pragma unroll
    for (int k = 0; k < 32; k++) wr[k] = w[j*32 + k];
    float bb = b[j];
    for (int t = 0; t < 16; t++) {
        float acc = bb;
        const float* zr = sz + t*33;
        #pragma unroll
        for (int k = 0; k < 32; k++) acc = fmaf(zr[k], wr[k], acc);
        h[(size_t)(tok0+t)*256 + j] = acc;
    }
}

// =====================================================================
// Mamba pieces
// =====================================================================
__global__ __launch_bounds__(256) void rmsnorm_kernel(const float* __restrict__ x,
                               const float* __restrict__ w,
                               float* __restrict__ out)
{
    int tok = blockIdx.x*8 + (threadIdx.x >> 5);
    int lane = threadIdx.x & 31;
    const float4* xr = (const float4*)(x + (size_t)tok*256);
    float4 v0 = xr[lane*2], v1 = xr[lane*2+1];
    float ss = v0.x*v0.x + v0.y*v0.y + v0.z*v0.z + v0.w*v0.w
             + v1.x*v1.x + v1.y*v1.y + v1.z*v1.z + v1.w*v1.w;
    #pragma unroll
    for (int o = 16; o > 0; o >>= 1) ss += __shfl_xor_sync(0xffffffffu, ss, o);
    float scale = rsqrtf(ss * (1.f/256.f) + 1e-5f);
    const float4* wr = (const float4*)w;
    float4 w0 = wr[lane*2], w1 = wr[lane*2+1];
    float4 o0, o1;
    o0.x = v0.x*scale*w0.x; o0.y = v0.y*scale*w0.y; o0.z = v0.z*scale*w0.z; o0.w = v0.w*scale*w0.w;
    o1.x = v1.x*scale*w1.x; o1.y = v1.y*scale*w1.y; o1.z = v1.z*scale*w1.z; o1.w = v1.w*scale*w1.w;
    float4* outr = (float4*)(out + (size_t)tok*256);
    outr[lane*2] = o0; outr[lane*2+1] = o1;
}

// tile 64x64, 256 thr, 4x4 micro, f32x2. EPI: 0 store
__global__ __launch_bounds__(256) void gemm64_kernel(const float* __restrict__ A,
                              const float* __restrict__ W,
                              float* __restrict__ C,
                              int M, int N, int K)
{
    __shared__ float As[16][68];
    __shared__ float Ws[16][68];
    int bm = blockIdx.y * 64;
    int bn = blockIdx.x * 64;
    int tid = threadIdx.x;
    int tx = tid & 15, ty = tid >> 4;
    u64 acc[4][2];
    #pragma unroll
    for (int i = 0; i < 4; i++) { acc[i][0] = 0ull; acc[i][1] = 0ull; }
    for (int k0 = 0; k0 < K; k0 += 16) {
        {
            int r = tid >> 2, c = tid & 3;
            float4 v = *(const float4*)&A[(size_t)(bm+r)*K + k0 + c*4];
            As[c*4+0][r] = v.x; As[c*4+1][r] = v.y; As[c*4+2][r] = v.z; As[c*4+3][r] = v.w;
            float4 u = *(const float4*)&W[(size_t)(bn+r)*K + k0 + c*4];
            Ws[c*4+0][r] = u.x; Ws[c*4+1][r] = u.y; Ws[c*4+2][r] = u.z; Ws[c*4+3][r] = u.w;
        }
        __syncthreads();
        #pragma unroll
        for (int k = 0; k < 16; k++) {
            float4 a0 = *(const float4*)&As[k][ty*4];
            F4U b0;
            b0.f = *(const float4*)&Ws[k][tx*4];
            u64 bp0 = b0.u[0], bp1 = b0.u[1];
            float av[4] = {a0.x, a0.y, a0.z, a0.w};
            #pragma unroll
            for (int i = 0; i < 4; i++) {
                u64 ad = pk2(av[i], av[i]);
                acc[i][0] = ffma2(ad, bp0, acc[i][0]);
                acc[i][1] = ffma2(ad, bp1, acc[i][1]);
            }
        }
        __syncthreads();
    }
    #pragma unroll
    for (int i = 0; i < 4; i++) {
        int m = bm + ty*4 + i;
        float2 v0 = upk2(acc[i][0]), v1 = upk2(acc[i][1]);
        *(float4*)&C[(size_t)m*N + bn + tx*4] = make_float4(v0.x, v0.y, v1.x, v1.y);
    }
}

// tile 32x64, 256 thr, 2x4 micro, f32x2. EPI: 1 accumulate, 2 bias+gelu
template<int EPI>
__global__ __launch_bounds__(256) void gemm32x64_kernel(const float* __restrict__ A,
                              const float* __restrict__ W,
                              const float* __restrict__ bias,
                              float* __restrict__ C,
                              int M, int N, int K)
{
    __shared__ float As[16][36];
    __shared__ float Ws[16][68];
    int bm = blockIdx.y * 32;
    int bn = blockIdx.x * 64;
    int tid = threadIdx.x;
    int tx = tid & 15, ty = tid >> 4;
    u64 acc[2][2];
    acc[0][0]=0ull; acc[0][1]=0ull; acc[1][0]=0ull; acc[1][1]=0ull;
    for (int k0 = 0; k0 < K; k0 += 16) {
        if (tid < 128) {
            int r = tid >> 2, c = tid & 3;
            float4 v = *(const float4*)&A[(size_t)(bm+r)*K + k0 + c*4];
            As[c*4+0][r] = v.x; As[c*4+1][r] = v.y; As[c*4+2][r] = v.z; As[c*4+3][r] = v.w;
        }
        {
            int r = tid >> 2, c = tid & 3;
            float4 u = *(const float4*)&W[(size_t)(bn+r)*K + k0 + c*4];
            Ws[c*4+0][r] = u.x; Ws[c*4+1][r] = u.y; Ws[c*4+2][r] = u.z; Ws[c*4+3][r] = u.w;
        }
        __syncthreads();
        #pragma unroll
        for (int k = 0; k < 16; k++) {
            float2 a0 = *(const float2*)&As[k][ty*2];
            F4U b0;
            b0.f = *(const float4*)&Ws[k][tx*4];
            u64 bp0 = b0.u[0], bp1 = b0.u[1];
            u64 ad0 = pk2(a0.x, a0.x);
            u64 ad1 = pk2(a0.y, a0.y);
            acc[0][0] = ffma2(ad0, bp0, acc[0][0]);
            acc[0][1] = ffma2(ad0, bp1, acc[0][1]);
            acc[1][0] = ffma2(ad1, bp0, acc[1][0]);
            acc[1][1] = ffma2(ad1, bp1, acc[1][1]);
        }
        __syncthreads();
    }
    #pragma unroll
    for (int i = 0; i < 2; i++) {
        int m = bm + ty*2 + i;
        float2 v0 = upk2(acc[i][0]), v1 = upk2(acc[i][1]);
        float vals[4] = {v0.x, v0.y, v1.x, v1.y};
        size_t base = (size_t)m*N + bn + tx*4;
        if (EPI == 1) {
            float4 old = *(float4*)&C[base];
            old.x += vals[0]; old.y += vals[1]; old.z += vals[2]; old.w += vals[3];
            *(float4*)&C[base] = old;
        } else {
            float4 o;
            float* op = &o.x;
            #pragma unroll
            for (int j = 0; j < 4; j++) {
                float v = vals[j] + bias[bn + tx*4 + j];
                float v3 = v*v*v;
                op[j] = 0.5f * v * (1.f + tanhf(0.7978845608028654f * (v + 0.044715f*v3)));
            }
            *(float4*)&C[base] = o;
        }
    }
}

__global__ __launch_bounds__(256) void conv1d_silu_kernel(const float* __restrict__ xz,
                                   const float* __restrict__ cw,
                                   const float* __restrict__ cb,
                                   float* __restrict__ xin)
{
    int idx = blockIdx.x * blockDim.x + threadIdx.x; // BT*DI
    int token = idx >> 9;
    int e = idx & 511;
    int t = token & 255;
    float acc = cb[e];
    const float* wk = cw + e*4;
    #pragma unroll
    for (int k = 0; k < 4; k++) {
        int tt = t - 3 + k;
        if (tt >= 0)
            acc = fmaf(xz[(size_t)(token - 3 + k)*1024 + e], wk[k], acc);
    }
    xin[idx] = acc / (1.f + __expf(-acc));
}

// Fused x_proj + dt_proj: per block 16 tokens.
// Phase A: dbc[16x48] = xin_tile . xpw^T -> dt to smem, (B,C) to global
// Phase B: delta = softplus(dt . dpw^T + dpb); du = (delta, u)
#define SXIDX(tok, k) ((tok)*512 + (((k) + (tok)*4) & 511))
__global__ __launch_bounds__(256) void xproj_fused_kernel(
    const float* __restrict__ xin,
    const float* __restrict__ xpw,
    const float* __restrict__ dpw,
    const float* __restrict__ dpb,
    float2* __restrict__ bc,
    float2* __restrict__ du)
{
    __shared__ float sx[16*512];     // swizzled
    __shared__ float buf[48*68];     // sw chunks (48x64) / dpw chunks (128x16=2048)
    __shared__ float sdt[16*16];
    int tok0 = blockIdx.x * 16;
    int tid = threadIdx.x;

    // load x tile (swizzled rows)
    #pragma unroll
    for (int s = 0; s < 8; s++) {
        int q = tid + s*256;          // float4 id 0..2047
        int t = q >> 7, kq = q & 127;
        float4 v = *(const float4*)&xin[(size_t)(tok0+t)*512 + kq*4];
        float* dst = sx + SXIDX(t, kq*4);
        dst[0]=v.x; dst[1]=v.y; dst[2]=v.z; dst[3]=v.w;
    }

    // Phase A
    int tg = tid & 15;       // token
    int jg = tid >> 4;       // 0..15 -> j = jg*3 + {0,1,2}
    int rot = tg*4;
    const float* sxr = sx + tg*512;
    float acc0 = 0.f, acc1 = 0.f, acc2 = 0.f;
    #pragma unroll 1
    for (int kc = 0; kc < 8; kc++) {
        int k0 = kc*64;
        __syncthreads();
        // load w chunk 48x64
        #pragma unroll
        for (int s = 0; s < 3; s++) {
            int q = tid + s*256;      // 0..767 float4
            int r = q >> 4, c = q & 15;
            float4 v = *(const float4*)&xpw[(size_t)r*512 + k0 + c*4];
            float* dst = buf + r*68 + c*4;
            dst[0]=v.x; dst[1]=v.y; dst[2]=v.z; dst[3]=v.w;
        }
        __syncthreads();
        const float* w0 = buf + (jg*3+0)*68;
        const float* w1 = buf + (jg*3+1)*68;
        const float* w2 = buf + (jg*3+2)*68;
        #pragma unroll 8
        for (int k = 0; k < 64; k++) {
            float xv = sxr[(k0 + k + rot) & 511];
            acc0 = fmaf(xv, w0[k], acc0);
            acc1 = fmaf(xv, w1[k], acc1);
            acc2 = fmaf(xv, w2[k], acc2);
        }
    }
    // scatter outputs
    {
        float av[3] = {acc0, acc1, acc2};
        #pragma unroll
        for (int jj = 0; jj < 3; jj++) {
            int j = jg*3 + jj;
            float v = av[jj];
            int tok = tok0 + tg;
            if (j < 16)       sdt[tg*16 + j] = v;
            else if (j < 32)  bc[tok*16 + (j-16)].x = v;
            else              bc[tok*16 + (j-32)].y = v;
        }
    }

    // Phase B: 4 chunks of 128 e
    #pragma unroll 1
    for (int ec = 0; ec < 4; ec++) {
        int e0 = ec*128;
        __syncthreads();
        // load dpw chunk 128x16 = 512 float4
        #pragma unroll
        for (int s = 0; s < 2; s++) {
            int q = tid + s*256;
            int r = q >> 2, c = q & 3;    // r 0..127, c 0..3
            float4 v = *(const float4*)&dpw[(size_t)(e0+r)*16 + c*4];
            float* dst = buf + r*16 + c*4;
            dst[0]=v.x; dst[1]=v.y; dst[2]=v.z; dst[3]=v.w;
        }
        __syncthreads();
        #pragma unroll 1
        for (int s = 0; s < 8; s++) {
            int idx = tid + s*256;        // 0..2047
            int e_l = idx & 127;
            int tok = idx >> 7;           // 0..15
            int e = e0 + e_l;
            const float* dr = sdt + tok*16;
            const float* wr = buf + e_l*16;
            float a = dpb[e];
            #pragma unroll
            for (int k = 0; k < 16; k++) a = fmaf(dr[k], wr[k], a);
            float sp = (a > 20.f) ? a : log1pf(expf(a));
            float u = sx[SXIDX(tok, e)];
            du[(size_t)(tok0+tok)*512 + e] = make_float2(sp, u);
        }
    }
}

__global__ __launch_bounds__(256) void scan_kernel(const float2* __restrict__ du,
                            const float* __restrict__ xz,
                            const float2* __restrict__ bc,
                            const float* __restrict__ A_log,
                            const float* __restrict__ Dp,
                            float* __restrict__ yout)
{
    int tid = blockIdx.x * blockDim.x + threadIdx.x;
    int ch = tid >> 4;
    int n = tid & 15;
    int b = ch >> 9;
    int e = ch & 511;
    float A  = -expf(A_log[e*16 + n]);
    float Dv = Dp[e];
    float h = 0.f;
    int tok0 = b * 256;
    for (int t = 0; t < 256; t++) {
        int tok = tok0 + t;
        float2 duv = du[(size_t)tok*512 + e];
        float2 bcv = bc[tok*16 + n];
        float dA = __expf(duv.x * A);
        h = fmaf(h, dA, duv.x * bcv.x * duv.y);
        float part = h * bcv.y;
        #pragma unroll
        for (int o = 8; o > 0; o >>= 1) part += __shfl_down_sync(0xffffffffu, part, o, 16);
        if (n == 0) {
            float zv = xz[(size_t)tok*1024 + 512 + e];
            float y = part + duv.y * Dv;
            yout[(size_t)tok*512 + e] = y * (zv / (1.f + __expf(-zv)));
        }
    }
}

// =====================================================================
// Head tail
// =====================================================================
__global__ __launch_bounds__(256) void head2_kernel(const float* __restrict__ hh,
                             const float* __restrict__ w,
                             const float* __restrict__ b,
                             float* __restrict__ logits)
{
    int wid = (blockIdx.x * blockDim.x + threadIdx.x) >> 5;
    int lane = threadIdx.x & 31;
    const float* xr = hh + (size_t)wid*64;
    float acc = fmaf(xr[lane], w[lane], xr[lane+32]*w[lane+32]);
    #pragma unroll
    for (int o = 16; o > 0; o >>= 1) acc += __shfl_down_sync(0xffffffffu, acc, o);
    if (lane == 0) logits[wid] = acc + b[0];
}

__global__ __launch_bounds__(256) void softmax_kernel(const float* __restrict__ logits,
                               float* __restrict__ out)
{
    int b = blockIdx.x;
    int t = threadIdx.x;
    float v = logits[b*256 + t];
    __shared__ float red[8];
    __shared__ float sM, sS;
    float m = v;
    #pragma unroll
    for (int o = 16; o > 0; o >>= 1) m = fmaxf(m, __shfl_xor_sync(0xffffffffu, m, o));
    if ((t & 31) == 0) red[t >> 5] = m;
    __syncthreads();
    if (t < 8) {
        float mm = red[t];
        #pragma unroll
        for (int o = 4; o > 0; o >>= 1) mm = fmaxf(mm, __shfl_xor_sync(0xffu, mm, o, 8));
        if (t == 0) sM = mm;
    }
    __syncthreads();
    float e = expf(v - sM);
    float s = e;
    #pragma unroll
    for (int o = 16; o > 0; o >>= 1) s += __shfl_xor_sync(0xffffffffu, s, o);
    __syncthreads();
    if ((t & 31) == 0) red[t >> 5] = s;
    __syncthreads();
    if (t < 8) {
        float ss2 = red[t];
        #pragma unroll
        for (int o = 4; o > 0; o >>= 1) ss2 += __shfl_xor_sync(0xffu, ss2, o, 8);
        if (t == 0) sS = ss2;
    }
    __syncthreads();
    out[b*256 + t] = (t == 0) ? 0.f : e / sS;
}

// =====================================================================
// Launcher
// =====================================================================
extern "C" void kernel_launch(void* const* d_in, const int* in_sizes, int n_in,
                              void* d_out, int out_size)
{
    (void)in_sizes; (void)n_in; (void)out_size;
    const float* x        = (const float*)d_in[0];
    const float* cnn_w1   = (const float*)d_in[1];
    const float* cnn_b1   = (const float*)d_in[2];
    const float* cnn_w2   = (const float*)d_in[3];
    const float* cnn_b2   = (const float*)d_in[4];
    const float* cnn_w3   = (const float*)d_in[5];
    const float* cnn_b3   = (const float*)d_in[6];
    const float* fc_w     = (const float*)d_in[7];
    const float* fc_b     = (const float*)d_in[8];
    const float* norm_w   = (const float*)d_in[9];
    const float* in_proj_w= (const float*)d_in[10];
    const float* conv1d_w = (const float*)d_in[11];
    const float* conv1d_b = (const float*)d_in[12];
    const float* x_proj_w = (const float*)d_in[13];
    const float* dt_proj_w= (const float*)d_in[14];
    const float* dt_proj_b= (const float*)d_in[15];
    const float* A_log    = (const float*)d_in[16];
    const float* Dp       = (const float*)d_in[17];
    const float* out_proj_w=(const float*)d_in[18];
    const float* norm_f_w = (const float*)d_in[19];
    const float* head_w1  = (const float*)d_in[20];
    const float* head_b1  = (const float*)d_in[21];
    const float* head_w2  = (const float*)d_in[22];
    const float* head_b2  = (const float*)d_in[23];
    float* out = (float*)d_out;

    float *f1, *f2, *z1, *h, *xn, *xz, *xin, *y, *hh, *logits;
    float2 *bc, *du;
    cudaGetSymbolAddress((void**)&f1, g_f1);
    cudaGetSymbolAddress((void**)&f2, g_f2);
    cudaGetSymbolAddress((void**)&z1, g_z1);
    cudaGetSymbolAddress((void**)&h,  g_h);
    cudaGetSymbolAddress((void**)&xn, g_xn);
    cudaGetSymbolAddress((void**)&xz, g_xz);
    cudaGetSymbolAddress((void**)&xin,g_xin);
    cudaGetSymbolAddress((void**)&bc, g_bc);
    cudaGetSymbolAddress((void**)&du, g_du);
    cudaGetSymbolAddress((void**)&y,  g_y);
    cudaGetSymbolAddress((void**)&hh, g_hh);
    cudaGetSymbolAddress((void**)&logits, g_logits);

    // --- CNN encoder ---
    conv1_kernel<<<2048, 512>>>(x, cnn_w1, cnn_b1, f1);
    conv2_kernel<<<2048, 256>>>(f1, cnn_w2, cnn_b2, f2);
    conv3pool_kernel<<<1024, 256>>>(f2, cnn_w3, cnn_b3, z1);
    fc_kernel<<<128, 256>>>(z1, fc_w, fc_b, h);

    // --- Mamba layers ---
    for (int l = 0; l < 6; l++) {
        const float* nw  = norm_w     + (size_t)l*DM;
        const float* ipw = in_proj_w  + (size_t)l*2*DI*DM;
        const float* cw  = conv1d_w   + (size_t)l*DI*4;
        const float* cb  = conv1d_b   + (size_t)l*DI;
        const float* xpw = x_proj_w   + (size_t)l*48*DI;
        const float* dpw = dt_proj_w  + (size_t)l*DI*DTR;
        const float* dpb = dt_proj_b  + (size_t)l*DI;
        const float* al  = A_log      + (size_t)l*DI*DS;
        const float* dv  = Dp         + (size_t)l*DI;
        const float* opw = out_proj_w + (size_t)l*DM*DI;

        rmsnorm_kernel<<<256, 256>>>(h, nw, xn);
        gemm64_kernel<<<dim3(16, 32), 256>>>(xn, ipw, xz, BT, 1024, 256);
        conv1d_silu_kernel<<<BT*DI/256, 256>>>(xz, cw, cb, xin);
        xproj_fused_kernel<<<128, 256>>>(xin, xpw, dpw, dpb, bc, du);
        scan_kernel<<<BATCH*DI*DS/256, 256>>>(du, xz, bc, al, dv, y);
        gemm32x64_kernel<1><<<dim3(4, 64), 256>>>(y, opw, nullptr, h, BT, 256, 512);
    }

    // --- Head ---
    rmsnorm_kernel<<<256, 256>>>(h, norm_f_w, xn);
    gemm32x64_kernel<2><<<dim3(1, 64), 256>>>(xn, head_w1, head_b1, hh, BT, 64, 256);
    head2_kernel<<<BT*32/256, 256>>>(hh, head_w2, head_b2, logits);
    softmax_kernel<<<BATCH, 256>>>(logits, out);
}

// round 5
// speedup vs baseline: 1.6585x; 1.3353x over previous
#include <cuda_runtime.h>
#include <math.h>

// ---- problem constants ----
#define BATCH   8
#define TT      256
#define BT      2048          // BATCH*TT
#define DM      256           // d_model
#define DI      512           // d_inner
#define DS      16            // d_state
#define DTR     16            // dt_rank

typedef unsigned long long u64;

__device__ __forceinline__ u64 pk2(float lo, float hi) {
    u64 d;
    asm("mov.b64 %0, {%1, %2};" : "=l"(d)
        : "r"(__float_as_uint(lo)), "r"(__float_as_uint(hi)));
    return d;
}
__device__ __forceinline__ u64 ffma2(u64 a, u64 b, u64 c) {
    u64 d;
    asm("fma.rn.f32x2 %0, %1, %2, %3;" : "=l"(d) : "l"(a), "l"(b), "l"(c));
    return d;
}
__device__ __forceinline__ float2 upk2(u64 v) {
    unsigned lo, hi;
    asm("mov.b64 {%0, %1}, %2;" : "=r"(lo), "=r"(hi) : "l"(v));
    return make_float2(__uint_as_float(lo), __uint_as_float(hi));
}
union F4U { float4 f; u64 u[2]; };

// ---- scratch ----
__device__ float  g_f1[2048*16*32*32];
__device__ float  g_f2[2048*32*16*16];
__device__ float  g_z1[2048*32];
__device__ float  g_h [BT*DM];
__device__ float  g_xn[BT*DM];
__device__ float  g_xz[BT*2*DI];
__device__ float2 g_bc[BT*DS];
__device__ float2 g_du[BT*DI];
__device__ float  g_y [BT*DI];
__device__ float  g_hh[BT*64];
__device__ float  g_logits[BT];

// =====================================================================
// CNN
// =====================================================================
__global__ __launch_bounds__(512) void conv1_kernel(const float* __restrict__ x,
                             const float* __restrict__ w,
                             const float* __restrict__ b,
                             float* __restrict__ out)
{
    __shared__ float sin[65*65];
    __shared__ float sw[144];
    __shared__ float sb[16];
    int f = blockIdx.x;
    const float* xf = x + (size_t)f*4096;
    for (int i = threadIdx.x; i < 65*65; i += 512) {
        int r = i / 65, c = i - r*65;
        sin[i] = (r < 64 && c < 64) ? xf[r*64+c] : 0.f;
    }
    if (threadIdx.x < 144) sw[threadIdx.x] = w[threadIdx.x];
    if (threadIdx.x < 16)  sb[threadIdx.x] = b[threadIdx.x];
    __syncthreads();
    int xg = threadIdx.x & 3;
    int oy = (threadIdx.x >> 2) & 31;
    int cq = threadIdx.x >> 7;
    float acc[4][8];
    #pragma unroll
    for (int c = 0; c < 4; c++) {
        float bb = sb[cq*4+c];
        #pragma unroll
        for (int q = 0; q < 8; q++) acc[c][q] = bb;
    }
    int i0 = oy*2, j0 = xg*16;
    #pragma unroll
    for (int ky = 0; ky < 3; ky++) {
        const float* rp = sin + (i0+ky)*65 + j0;
        float r[17];
        #pragma unroll
        for (int t = 0; t < 17; t++) r[t] = rp[t];
        #pragma unroll
        for (int c = 0; c < 4; c++) {
            const float* wp = sw + (cq*4+c)*9 + ky*3;
            float w0 = wp[0], w1 = wp[1], w2 = wp[2];
            #pragma unroll
            for (int q = 0; q < 8; q++)
                acc[c][q] = fmaf(r[2*q],w0, fmaf(r[2*q+1],w1, fmaf(r[2*q+2],w2, acc[c][q])));
        }
    }
    #pragma unroll
    for (int c = 0; c < 4; c++)
        #pragma unroll
        for (int q = 0; q < 8; q++)
            out[((size_t)f*16 + cq*4+c)*1024 + oy*32 + xg*8 + q] = fmaxf(acc[c][q], 0.f);
}

__global__ __launch_bounds__(256) void conv2_kernel(const float* __restrict__ in,
                             const float* __restrict__ w,
                             const float* __restrict__ b,
                             float* __restrict__ out)
{
    // in (2048,16,32,32) -> out (2048,32,16,16), f32x2 packed FMA
    __shared__ float sin[8*33*34];
    __shared__ float sw[2304];
    int f = blockIdx.x;
    int tid = threadIdx.x;
    int cg  = tid >> 5;
    int lane = tid & 31;
    int oy = lane >> 1;
    int xh = lane & 1;
    u64 acc2[4][4];
    #pragma unroll
    for (int c = 0; c < 4; c++) {
        float bb = __ldg(&b[cg*4+c]);
        u64 bp = pk2(bb, bb);
        #pragma unroll
        for (int p = 0; p < 4; p++) acc2[c][p] = bp;
    }
    #pragma unroll 1
    for (int pass = 0; pass < 2; pass++) {
        int ci0 = pass*8;
        __syncthreads();
        for (int idx = tid; idx < 8*33*33; idx += 256) {
            int ci = idx / 1089;
            int rem = idx - ci*1089;
            int i = rem / 33, j = rem - i*33;
            sin[ci*1122 + i*34 + j] = (i < 32 && j < 32)
                ? in[(size_t)f*16384 + (ci0+ci)*1024 + i*32 + j] : 0.f;
        }
        for (int idx = tid; idx < 2304; idx += 256) {
            int co = idx / 72;
            int rem = idx - co*72;
            int ci_l = rem / 9, k = rem - ci_l*9;
            sw[idx] = w[(co*16 + ci0 + ci_l)*9 + k];
        }
        __syncthreads();
        #pragma unroll 1
        for (int ci = 0; ci < 8; ci++) {
            const float* base = sin + ci*1122 + (2*oy)*34 + xh*16;
            #pragma unroll
            for (int row = 0; row < 3; row++) {
                const float* rp = base + row*34;
                float r[17];
                #pragma unroll
                for (int t = 0; t < 17; t++) r[t] = rp[t];
                u64 pr[12];
                #pragma unroll
                for (int p = 0; p < 4; p++)
                    #pragma unroll
                    for (int l = 0; l < 3; l++)
                        pr[p*3+l] = pk2(r[p*4+l], r[p*4+l+2]);
                #pragma unroll
                for (int c = 0; c < 4; c++) {
                    const float* wp = sw + (cg*4+c)*72 + ci*9 + row*3;
                    u64 wd0 = pk2(wp[0], wp[0]);
                    u64 wd1 = pk2(wp[1], wp[1]);
                    u64 wd2 = pk2(wp[2], wp[2]);
                    #pragma unroll
                    for (int p = 0; p < 4; p++) {
                        acc2[c][p] = ffma2(pr[p*3+0], wd0, acc2[c][p]);
                        acc2[c][p] = ffma2(pr[p*3+1], wd1, acc2[c][p]);
                        acc2[c][p] = ffma2(pr[p*3+2], wd2, acc2[c][p]);
                    }
                }
            }
        }
    }
    #pragma unroll
    for (int c = 0; c < 4; c++)
        #pragma unroll
        for (int p = 0; p < 4; p++) {
            float2 v = upk2(acc2[c][p]);
            float2 o = make_float2(fmaxf(v.x, 0.f), fmaxf(v.y, 0.f));
            *(float2*)&out[((size_t)f*32 + cg*4+c)*256 + oy*16 + xh*8 + 2*p] = o;
        }
}

__global__ __launch_bounds__(256) void conv3pool_kernel(const float* __restrict__ in,
                                 const float* __restrict__ w,
                                 const float* __restrict__ b,
                                 float* __restrict__ z1)
{
    __shared__ float sin[2*8*17*18];
    __shared__ float sw[32*8*9];
    int f0 = blockIdx.x * 2;
    int tid = threadIdx.x;
    int fr = tid >> 7;
    int t  = tid & 127;
    int cg = t >> 4;
    int oy = (t >> 1) & 7;
    int xh = t & 1;
    u64 acc2[4][2];
    #pragma unroll
    for (int c = 0; c < 4; c++) {
        float bb = __ldg(&b[cg*4+c]);
        u64 bp = pk2(bb, bb);
        acc2[c][0] = bp; acc2[c][1] = bp;
    }
    #pragma unroll 1
    for (int pass = 0; pass < 4; pass++) {
        int ci0 = pass*8;
        __syncthreads();
        for (int idx = tid; idx < 2*8*17*17; idx += 256) {
            int fr2 = idx / 2312;
            int rem = idx - fr2*2312;
            int ci = rem / 289;
            int r2 = rem - ci*289;
            int i = r2 / 17, j = r2 - i*17;
            sin[fr2*2448 + ci*306 + i*18 + j] = (i < 16 && j < 16)
                ? in[(size_t)(f0+fr2)*8192 + (ci0+ci)*256 + i*16 + j] : 0.f;
        }
        for (int idx = tid; idx < 2304; idx += 256) {
            int co = idx / 72;
            int rem = idx - co*72;
            int ci_l = rem / 9, k = rem - ci_l*9;
            sw[idx] = w[(co*32 + ci0 + ci_l)*9 + k];
        }
        __syncthreads();
        #pragma unroll 1
        for (int ci = 0; ci < 8; ci++) {
            const float* base = sin + fr*2448 + ci*306 + (2*oy)*18 + xh*8;
            #pragma unroll
            for (int row = 0; row < 3; row++) {
                const float* rp = base + row*18;
                float r[9];
                #pragma unroll
                for (int q = 0; q < 9; q++) r[q] = rp[q];
                u64 pr[6];
                #pragma unroll
                for (int p = 0; p < 2; p++)
                    #pragma unroll
                    for (int l = 0; l < 3; l++)
                        pr[p*3+l] = pk2(r[p*4+l], r[p*4+l+2]);
                #pragma unroll
                for (int c = 0; c < 4; c++) {
                    const float* wp = sw + (cg*4+c)*72 + ci*9 + row*3;
                    u64 wd0 = pk2(wp[0], wp[0]);
                    u64 wd1 = pk2(wp[1], wp[1]);
                    u64 wd2 = pk2(wp[2], wp[2]);
                    #pragma unroll
                    for (int p = 0; p < 2; p++) {
                        acc2[c][p] = ffma2(pr[p*3+0], wd0, acc2[c][p]);
                        acc2[c][p] = ffma2(pr[p*3+1], wd1, acc2[c][p]);
                        acc2[c][p] = ffma2(pr[p*3+2], wd2, acc2[c][p]);
                    }
                }
            }
        }
    }
    #pragma unroll
    for (int c = 0; c < 4; c++) {
        float2 v0 = upk2(acc2[c][0]), v1 = upk2(acc2[c][1]);
        float s = fmaxf(v0.x,0.f) + fmaxf(v0.y,0.f) + fmaxf(v1.x,0.f) + fmaxf(v1.y,0.f);
        #pragma unroll
        for (int o = 8; o > 0; o >>= 1) s += __shfl_down_sync(0xffffffffu, s, o, 16);
        if (oy == 0 && xh == 0) z1[(f0+fr)*32 + cg*4 + c] = s * (1.f/64.f);
    }
}

__global__ __launch_bounds__(256) void fc_kernel(const float* __restrict__ z1,
                          const float* __restrict__ w,
                          const float* __restrict__ b,
                          float* __restrict__ h)
{
    // 16 tokens per block, 128 blocks; weights staged through smem (coalesced)
    __shared__ float sw[256*33];
    __shared__ float sz[16*33];
    int tok0 = blockIdx.x * 16;
    int j = threadIdx.x;
    for (int idx = threadIdx.x; idx < 8192; idx += 256) {
        int r = idx >> 5, k = idx & 31;
        sw[r*33 + k] = w[idx];
    }
    for (int idx = threadIdx.x; idx < 512; idx += 256) {
        int t = idx >> 5, k = idx & 31;
        sz[t*33 + k] = z1[(tok0+t)*32 + k];
    }
    __syncthreads();
    float wr[32];
    #pragma unroll
    for (int k = 0; k < 32; k++) wr[k] = sw[j*33 + k];
    float bb = b[j];
    for (int t = 0; t < 16; t++) {
        float acc = bb;
        const float* zr = sz + t*33;
        #pragma unroll
        for (int k = 0; k < 32; k++) acc = fmaf(zr[k], wr[k], acc);
        h[(size_t)(tok0+t)*256 + j] = acc;
    }
}

// =====================================================================
// Mamba pieces
// =====================================================================
__global__ __launch_bounds__(256) void rmsnorm_kernel(const float* __restrict__ x,
                               const float* __restrict__ w,
                               float* __restrict__ out)
{
    int tok = blockIdx.x*8 + (threadIdx.x >> 5);
    int lane = threadIdx.x & 31;
    const float4* xr = (const float4*)(x + (size_t)tok*256);
    float4 v0 = xr[lane*2], v1 = xr[lane*2+1];
    float ss = v0.x*v0.x + v0.y*v0.y + v0.z*v0.z + v0.w*v0.w
             + v1.x*v1.x + v1.y*v1.y + v1.z*v1.z + v1.w*v1.w;
    #pragma unroll
    for (int o = 16; o > 0; o >>= 1) ss += __shfl_xor_sync(0xffffffffu, ss, o);
    float scale = rsqrtf(ss * (1.f/256.f) + 1e-5f);
    const float4* wr = (const float4*)w;
    float4 w0 = wr[lane*2], w1 = wr[lane*2+1];
    float4 o0, o1;
    o0.x = v0.x*scale*w0.x; o0.y = v0.y*scale*w0.y; o0.z = v0.z*scale*w0.z; o0.w = v0.w*scale*w0.w;
    o1.x = v1.x*scale*w1.x; o1.y = v1.y*scale*w1.y; o1.z = v1.z*scale*w1.z; o1.w = v1.w*scale*w1.w;
    float4* outr = (float4*)(out + (size_t)tok*256);
    outr[lane*2] = o0; outr[lane*2+1] = o1;
}

// tile 64x64, 256 thr, 4x4 micro, f32x2 (plain store)
__global__ __launch_bounds__(256) void gemm64_kernel(const float* __restrict__ A,
                              const float* __restrict__ W,
                              float* __restrict__ C,
                              int M, int N, int K)
{
    __shared__ float As[16][68];
    __shared__ float Ws[16][68];
    int bm = blockIdx.y * 64;
    int bn = blockIdx.x * 64;
    int tid = threadIdx.x;
    int tx = tid & 15, ty = tid >> 4;
    u64 acc[4][2];
    #pragma unroll
    for (int i = 0; i < 4; i++) { acc[i][0] = 0ull; acc[i][1] = 0ull; }
    for (int k0 = 0; k0 < K; k0 += 16) {
        {
            int r = tid >> 2, c = tid & 3;
            float4 v = *(const float4*)&A[(size_t)(bm+r)*K + k0 + c*4];
            As[c*4+0][r] = v.x; As[c*4+1][r] = v.y; As[c*4+2][r] = v.z; As[c*4+3][r] = v.w;
            float4 u = *(const float4*)&W[(size_t)(bn+r)*K + k0 + c*4];
            Ws[c*4+0][r] = u.x; Ws[c*4+1][r] = u.y; Ws[c*4+2][r] = u.z; Ws[c*4+3][r] = u.w;
        }
        __syncthreads();
        #pragma unroll
        for (int k = 0; k < 16; k++) {
            float4 a0 = *(const float4*)&As[k][ty*4];
            F4U b0;
            b0.f = *(const float4*)&Ws[k][tx*4];
            u64 bp0 = b0.u[0], bp1 = b0.u[1];
            float av[4] = {a0.x, a0.y, a0.z, a0.w};
            #pragma unroll
            for (int i = 0; i < 4; i++) {
                u64 ad = pk2(av[i], av[i]);
                acc[i][0] = ffma2(ad, bp0, acc[i][0]);
                acc[i][1] = ffma2(ad, bp1, acc[i][1]);
            }
        }
        __syncthreads();
    }
    #pragma unroll
    for (int i = 0; i < 4; i++) {
        int m = bm + ty*4 + i;
        float2 v0 = upk2(acc[i][0]), v1 = upk2(acc[i][1]);
        *(float4*)&C[(size_t)m*N + bn + tx*4] = make_float4(v0.x, v0.y, v1.x, v1.y);
    }
}

// tile 32x64, 256 thr, 2x4 micro, f32x2. EPI: 1 accumulate, 2 bias+gelu
template<int EPI>
__global__ __launch_bounds__(256) void gemm32x64_kernel(const float* __restrict__ A,
                              const float* __restrict__ W,
                              const float* __restrict__ bias,
                              float* __restrict__ C,
                              int M, int N, int K)
{
    __shared__ float As[16][36];
    __shared__ float Ws[16][68];
    int bm = blockIdx.y * 32;
    int bn = blockIdx.x * 64;
    int tid = threadIdx.x;
    int tx = tid & 15, ty = tid >> 4;
    u64 acc[2][2];
    acc[0][0]=0ull; acc[0][1]=0ull; acc[1][0]=0ull; acc[1][1]=0ull;
    for (int k0 = 0; k0 < K; k0 += 16) {
        if (tid < 128) {
            int r = tid >> 2, c = tid & 3;
            float4 v = *(const float4*)&A[(size_t)(bm+r)*K + k0 + c*4];
            As[c*4+0][r] = v.x; As[c*4+1][r] = v.y; As[c*4+2][r] = v.z; As[c*4+3][r] = v.w;
        }
        {
            int r = tid >> 2, c = tid & 3;
            float4 u = *(const float4*)&W[(size_t)(bn+r)*K + k0 + c*4];
            Ws[c*4+0][r] = u.x; Ws[c*4+1][r] = u.y; Ws[c*4+2][r] = u.z; Ws[c*4+3][r] = u.w;
        }
        __syncthreads();
        #pragma unroll
        for (int k = 0; k < 16; k++) {
            float2 a0 = *(const float2*)&As[k][ty*2];
            F4U b0;
            b0.f = *(const float4*)&Ws[k][tx*4];
            u64 bp0 = b0.u[0], bp1 = b0.u[1];
            u64 ad0 = pk2(a0.x, a0.x);
            u64 ad1 = pk2(a0.y, a0.y);
            acc[0][0] = ffma2(ad0, bp0, acc[0][0]);
            acc[0][1] = ffma2(ad0, bp1, acc[0][1]);
            acc[1][0] = ffma2(ad1, bp0, acc[1][0]);
            acc[1][1] = ffma2(ad1, bp1, acc[1][1]);
        }
        __syncthreads();
    }
    #pragma unroll
    for (int i = 0; i < 2; i++) {
        int m = bm + ty*2 + i;
        float2 v0 = upk2(acc[i][0]), v1 = upk2(acc[i][1]);
        float vals[4] = {v0.x, v0.y, v1.x, v1.y};
        size_t base = (size_t)m*N + bn + tx*4;
        if (EPI == 1) {
            float4 old = *(float4*)&C[base];
            old.x += vals[0]; old.y += vals[1]; old.z += vals[2]; old.w += vals[3];
            *(float4*)&C[base] = old;
        } else {
            float4 o;
            float* op = &o.x;
            #pragma unroll
            for (int j = 0; j < 4; j++) {
                float v = vals[j] + bias[bn + tx*4 + j];
                float v3 = v*v*v;
                op[j] = 0.5f * v * (1.f + tanhf(0.7978845608028654f * (v + 0.044715f*v3)));
            }
            *(float4*)&C[base] = o;
        }
    }
}

// Fused conv1d+silu + x_proj + dt_proj: per block 16 tokens.
#define SXIDX(tok, k) ((tok)*512 + (((k) + (tok)*4) & 511))
__global__ __launch_bounds__(256) void xproj_fused_kernel(
    const float* __restrict__ xz,
    const float* __restrict__ cw,
    const float* __restrict__ cb,
    const float* __restrict__ xpw,
    const float* __restrict__ dpw,
    const float* __restrict__ dpb,
    float2* __restrict__ bc,
    float2* __restrict__ du)
{
    __shared__ float sx[16*512];     // xin tile, swizzled rows
    __shared__ float buf[48*68];     // conv w / xpw chunks / dpw chunks
    __shared__ float sdt[16*16];
    int tok0 = blockIdx.x * 16;
    int tid = threadIdx.x;

    // ---- Phase -1: conv1d + silu directly from xz into sx ----
    // conv weights transposed into buf: buf[k*512+e] = cw[e*4+k]; cb at buf+2048
    for (int idx = tid; idx < 2048; idx += 256) {
        int e = idx >> 2, k = idx & 3;
        buf[k*512 + e] = cw[idx];
    }
    for (int idx = tid; idx < 512; idx += 256) buf[2048 + idx] = cb[idx];
    __syncthreads();
    int tl0 = tok0 & 255;
    #pragma unroll 1
    for (int s = 0; s < 8; s++) {
        int q = tid + s*256;          // 0..2047 float4-outputs
        int t = q >> 7;               // token 0..15
        int e4 = q & 127;
        int e = e4*4;
        float4 acc = *(const float4*)&buf[2048 + e];
        #pragma unroll
        for (int k = 0; k < 4; k++) {
            if (tl0 + t - 3 + k >= 0) {
                float4 xv = *(const float4*)&xz[(size_t)(tok0 + t - 3 + k)*1024 + e];
                float4 wv = *(const float4*)&buf[k*512 + e];
                acc.x = fmaf(xv.x, wv.x, acc.x);
                acc.y = fmaf(xv.y, wv.y, acc.y);
                acc.z = fmaf(xv.z, wv.z, acc.z);
                acc.w = fmaf(xv.w, wv.w, acc.w);
            }
        }
        acc.x = acc.x / (1.f + __expf(-acc.x));
        acc.y = acc.y / (1.f + __expf(-acc.y));
        acc.z = acc.z / (1.f + __expf(-acc.z));
        acc.w = acc.w / (1.f + __expf(-acc.w));
        *(float4*)&sx[SXIDX(t, e)] = acc;
    }

    // ---- Phase A: dbc = xin . xpw^T ----
    int tg = tid & 15;       // token
    int jg = tid >> 4;       // 0..15 -> j = jg*3 + {0,1,2}
    int rot = tg*4;
    const float* sxr = sx + tg*512;
    float acc0 = 0.f, acc1 = 0.f, acc2 = 0.f;
    #pragma unroll 1
    for (int kc = 0; kc < 8; kc++) {
        int k0 = kc*64;
        __syncthreads();
        #pragma unroll
        for (int s = 0; s < 3; s++) {
            int q = tid + s*256;      // 0..767 float4
            int r = q >> 4, c = q & 15;
            float4 v = *(const float4*)&xpw[(size_t)r*512 + k0 + c*4];
            float* dst = buf + r*68 + c*4;
            dst[0]=v.x; dst[1]=v.y; dst[2]=v.z; dst[3]=v.w;
        }
        __syncthreads();
        const float* w0 = buf + (jg*3+0)*68;
        const float* w1 = buf + (jg*3+1)*68;
        const float* w2 = buf + (jg*3+2)*68;
        #pragma unroll 8
        for (int k = 0; k < 64; k++) {
            float xv = sxr[(k0 + k + rot) & 511];
            acc0 = fmaf(xv, w0[k], acc0);
            acc1 = fmaf(xv, w1[k], acc1);
            acc2 = fmaf(xv, w2[k], acc2);
        }
    }
    {
        float av[3] = {acc0, acc1, acc2};
        #pragma unroll
        for (int jj = 0; jj < 3; jj++) {
            int j = jg*3 + jj;
            float v = av[jj];
            int tok = tok0 + tg;
            if (j < 16)       sdt[tg*16 + j] = v;
            else if (j < 32)  bc[tok*16 + (j-16)].x = v;
            else              bc[tok*16 + (j-32)].y = v;
        }
    }

    // ---- Phase B: delta = softplus(dt . dpw^T + dpb); du = (delta, u) ----
    #pragma unroll 1
    for (int ec = 0; ec < 4; ec++) {
        int e0 = ec*128;
        __syncthreads();
        #pragma unroll
        for (int s = 0; s < 2; s++) {
            int q = tid + s*256;
            int r = q >> 2, c = q & 3;
            float4 v = *(const float4*)&dpw[(size_t)(e0+r)*16 + c*4];
            float* dst = buf + r*16 + c*4;
            dst[0]=v.x; dst[1]=v.y; dst[2]=v.z; dst[3]=v.w;
        }
        __syncthreads();
        #pragma unroll 1
        for (int s = 0; s < 8; s++) {
            int idx = tid + s*256;
            int e_l = idx & 127;
            int tok = idx >> 7;
            int e = e0 + e_l;
            const float* dr = sdt + tok*16;
            const float* wr = buf + e_l*16;
            float a = dpb[e];
            #pragma unroll
            for (int k = 0; k < 16; k++) a = fmaf(dr[k], wr[k], a);
            float sp = (a > 20.f) ? a : log1pf(expf(a));
            float u = sx[SXIDX(tok, e)];
            du[(size_t)(tok0+tok)*512 + e] = make_float2(sp, u);
        }
    }
}

// Selective scan: chunked register prefetch + pipelined shfl reduction
__global__ __launch_bounds__(256) void scan_kernel(const float2* __restrict__ du,
                            const float* __restrict__ xz,
                            const float2* __restrict__ bc,
                            const float* __restrict__ A_log,
                            const float* __restrict__ Dp,
                            float* __restrict__ yout)
{
    int tid = blockIdx.x * blockDim.x + threadIdx.x;
    int ch = tid >> 4;
    int n = tid & 15;
    int b = ch >> 9;
    int e = ch & 511;
    float A  = -expf(A_log[e*16 + n]);
    float Dv = Dp[e];
    const float2* duP = du + (size_t)(b*256)*512 + e;
    const float2* bcP = bc + (size_t)(b*256)*16 + n;
    const float*  zP  = xz + (size_t)(b*256)*1024 + 512 + e;
    float* yP = yout + (size_t)(b*256)*512 + e;

    float2 dv[2][8], bv[2][8];
    float  zv[2][8];
    #pragma unroll
    for (int i = 0; i < 8; i++) {
        dv[0][i] = duP[i*512];
        bv[0][i] = bcP[i*16];
        zv[0][i] = zP[i*1024];
    }
    float h = 0.f;
    int buf = 0;
    #pragma unroll 1
    for (int c = 0; c < 32; c++) {
        int nb = buf ^ 1;
        if (c < 31) {
            int t1 = c*8 + 8;
            #pragma unroll
            for (int i = 0; i < 8; i++) {
                dv[nb][i] = duP[(t1+i)*512];
                bv[nb][i] = bcP[(t1+i)*16];
                zv[nb][i] = zP[(size_t)(t1+i)*1024];
            }
        }
        float part[8];
        #pragma unroll
        for (int i = 0; i < 8; i++) {
            float2 duv = dv[buf][i];
            float2 bcv = bv[buf][i];
            float dA = __expf(duv.x * A);
            h = fmaf(h, dA, duv.x * bcv.x * duv.y);
            part[i] = h * bcv.y;
        }
        // stage-pipelined tree reduce over 16 lanes
        #pragma unroll
        for (int o = 8; o > 0; o >>= 1) {
            #pragma unroll
            for (int i = 0; i < 8; i++)
                part[i] += __shfl_down_sync(0xffffffffu, part[i], o, 16);
        }
        if (n == 0) {
            #pragma unroll
            for (int i = 0; i < 8; i++) {
                float z = zv[buf][i];
                float yy = part[i] + dv[buf][i].y * Dv;
                yP[(size_t)(c*8+i)*512] = yy * (z / (1.f + __expf(-z)));
            }
        }
        buf = nb;
    }
}

// =====================================================================
// Head tail
// =====================================================================
__global__ __launch_bounds__(256) void head2_kernel(const float* __restrict__ hh,
                             const float* __restrict__ w,
                             const float* __restrict__ b,
                             float* __restrict__ logits)
{
    int wid = (blockIdx.x * blockDim.x + threadIdx.x) >> 5;
    int lane = threadIdx.x & 31;
    const float* xr = hh + (size_t)wid*64;
    float acc = fmaf(xr[lane], w[lane], xr[lane+32]*w[lane+32]);
    #pragma unroll
    for (int o = 16; o > 0; o >>= 1) acc += __shfl_down_sync(0xffffffffu, acc, o);
    if (lane == 0) logits[wid] = acc + b[0];
}

__global__ __launch_bounds__(256) void softmax_kernel(const float* __restrict__ logits,
                               float* __restrict__ out)
{
    int b = blockIdx.x;
    int t = threadIdx.x;
    float v = logits[b*256 + t];
    __shared__ float red[8];
    __shared__ float sM, sS;
    float m = v;
    #pragma unroll
    for (int o = 16; o > 0; o >>= 1) m = fmaxf(m, __shfl_xor_sync(0xffffffffu, m, o));
    if ((t & 31) == 0) red[t >> 5] = m;
    __syncthreads();
    if (t < 8) {
        float mm = red[t];
        #pragma unroll
        for (int o = 4; o > 0; o >>= 1) mm = fmaxf(mm, __shfl_xor_sync(0xffu, mm, o, 8));
        if (t == 0) sM = mm;
    }
    __syncthreads();
    float e = expf(v - sM);
    float s = e;
    #pragma unroll
    for (int o = 16; o > 0; o >>= 1) s += __shfl_xor_sync(0xffffffffu, s, o);
    __syncthreads();
    if ((t & 31) == 0) red[t >> 5] = s;
    __syncthreads();
    if (t < 8) {
        float ss2 = red[t];
        #pragma unroll
        for (int o = 4; o > 0; o >>= 1) ss2 += __shfl_xor_sync(0xffu, ss2, o, 8);
        if (t == 0) sS = ss2;
    }
    __syncthreads();
    out[b*256 + t] = (t == 0) ? 0.f : e / sS;
}

// =====================================================================
// Launcher
// =====================================================================
extern "C" void kernel_launch(void* const* d_in, const int* in_sizes, int n_in,
                              void* d_out, int out_size)
{
    (void)in_sizes; (void)n_in; (void)out_size;
    const float* x        = (const float*)d_in[0];
    const float* cnn_w1   = (const float*)d_in[1];
    const float* cnn_b1   = (const float*)d_in[2];
    const float* cnn_w2   = (const float*)d_in[3];
    const float* cnn_b2   = (const float*)d_in[4];
    const float* cnn_w3   = (const float*)d_in[5];
    const float* cnn_b3   = (const float*)d_in[6];
    const float* fc_w     = (const float*)d_in[7];
    const float* fc_b     = (const float*)d_in[8];
    const float* norm_w   = (const float*)d_in[9];
    const float* in_proj_w= (const float*)d_in[10];
    const float* conv1d_w = (const float*)d_in[11];
    const float* conv1d_b = (const float*)d_in[12];
    const float* x_proj_w = (const float*)d_in[13];
    const float* dt_proj_w= (const float*)d_in[14];
    const float* dt_proj_b= (const float*)d_in[15];
    const float* A_log    = (const float*)d_in[16];
    const float* Dp       = (const float*)d_in[17];
    const float* out_proj_w=(const float*)d_in[18];
    const float* norm_f_w = (const float*)d_in[19];
    const float* head_w1  = (const float*)d_in[20];
    const float* head_b1  = (const float*)d_in[21];
    const float* head_w2  = (const float*)d_in[22];
    const float* head_b2  = (const float*)d_in[23];
    float* out = (float*)d_out;

    float *f1, *f2, *z1, *h, *xn, *xz, *y, *hh, *logits;
    float2 *bc, *du;
    cudaGetSymbolAddress((void**)&f1, g_f1);
    cudaGetSymbolAddress((void**)&f2, g_f2);
    cudaGetSymbolAddress((void**)&z1, g_z1);
    cudaGetSymbolAddress((void**)&h,  g_h);
    cudaGetSymbolAddress((void**)&xn, g_xn);
    cudaGetSymbolAddress((void**)&xz, g_xz);
    cudaGetSymbolAddress((void**)&bc, g_bc);
    cudaGetSymbolAddress((void**)&du, g_du);
    cudaGetSymbolAddress((void**)&y,  g_y);
    cudaGetSymbolAddress((void**)&hh, g_hh);
    cudaGetSymbolAddress((void**)&logits, g_logits);

    // --- CNN encoder ---
    conv1_kernel<<<2048, 512>>>(x, cnn_w1, cnn_b1, f1);
    conv2_kernel<<<2048, 256>>>(f1, cnn_w2, cnn_b2, f2);
    conv3pool_kernel<<<1024, 256>>>(f2, cnn_w3, cnn_b3, z1);
    fc_kernel<<<128, 256>>>(z1, fc_w, fc_b, h);

    // --- Mamba layers ---
    for (int l = 0; l < 6; l++) {
        const float* nw  = norm_w     + (size_t)l*DM;
        const float* ipw = in_proj_w  + (size_t)l*2*DI*DM;
        const float* cw  = conv1d_w   + (size_t)l*DI*4;
        const float* cb  = conv1d_b   + (size_t)l*DI;
        const float* xpw = x_proj_w   + (size_t)l*48*DI;
        const float* dpw = dt_proj_w  + (size_t)l*DI*DTR;
        const float* dpb = dt_proj_b  + (size_t)l*DI;
        const float* al  = A_log      + (size_t)l*DI*DS;
        const float* dv  = Dp         + (size_t)l*DI;
        const float* opw = out_proj_w + (size_t)l*DM*DI;

        rmsnorm_kernel<<<256, 256>>>(h, nw, xn);
        gemm64_kernel<<<dim3(16, 32), 256>>>(xn, ipw, xz, BT, 1024, 256);
        xproj_fused_kernel<<<128, 256>>>(xz, cw, cb, xpw, dpw, dpb, bc, du);
        scan_kernel<<<BATCH*DI*DS/256, 256>>>(du, xz, bc, al, dv, y);
        gemm32x64_kernel<1><<<dim3(4, 64), 256>>>(y, opw, nullptr, h, BT, 256, 512);
    }

    // --- Head ---
    rmsnorm_kernel<<<256, 256>>>(h, norm_f_w, xn);
    gemm32x64_kernel<2><<<dim3(1, 64), 256>>>(xn, head_w1, head_b1, hh, BT, 64, 256);
    head2_kernel<<<BT*32/256, 256>>>(hh, head_w2, head_b2, logits);
    softmax_kernel<<<BATCH, 256>>>(logits, out);
}